// round 4
// baseline (speedup 1.0000x reference)
#include <cuda_runtime.h>
#include <math.h>
#include <stdint.h>

// ---------------------------------------------------------------------------
// B=2, H=W=512. Three variants (iout, igt, icomp) -> 6 NCHW images.
// n = v*2 + b, v: 0=out, 1=gt, 2=comp.
// ---------------------------------------------------------------------------
#define HW0 (512*512)

__device__ float g_x0  [6*3*HW0];
__device__ float g_bufA[6*64*HW0];
__device__ float g_bufB[6*64*HW0];
__device__ float g_p1  [6*64*256*256];
__device__ float g_p2  [6*128*128*128];
__device__ float g_p3  [6*256*64*64];
__device__ double g_acc[4];   // 0:hole 1:valid 2:perc(raw) 3:style(scaled)

typedef unsigned long long u64;

// ---- packed f32x2 helpers --------------------------------------------------
__device__ __forceinline__ u64 pk(float lo, float hi) {
    u64 r; asm("mov.b64 %0,{%1,%2};" : "=l"(r) : "f"(lo), "f"(hi)); return r;
}
__device__ __forceinline__ float2 upk(u64 v) {
    float2 r; asm("mov.b64 {%0,%1},%2;" : "=f"(r.x), "=f"(r.y) : "l"(v)); return r;
}
__device__ __forceinline__ u64 fma2(u64 a, u64 b, u64 c) {
    u64 d; asm("fma.rn.f32x2 %0,%1,%2,%3;" : "=l"(d) : "l"(a), "l"(b), "l"(c)); return d;
}

// ---- cp.async helpers ------------------------------------------------------
__device__ __forceinline__ void cp4(uint32_t s, const float* g, bool ok) {
    asm volatile("cp.async.ca.shared.global [%0],[%1],4,%2;"
                 :: "r"(s), "l"(g), "r"(ok ? 4 : 0));
}
__device__ __forceinline__ void cp_commit() { asm volatile("cp.async.commit_group;"); }
template<int N> __device__ __forceinline__ void cp_wait() {
    asm volatile("cp.async.wait_group %0;" :: "n"(N));
}

// ---------------------------------------------------------------------------
__device__ __forceinline__ double blockReduceSum(double v) {
    __shared__ double s[32];
    int lane = threadIdx.x & 31, wid = threadIdx.x >> 5;
    #pragma unroll
    for (int o = 16; o; o >>= 1) v += __shfl_down_sync(0xffffffffu, v, o);
    if (lane == 0) s[wid] = v;
    __syncthreads();
    int nw = blockDim.x >> 5;
    v = (threadIdx.x < nw) ? s[threadIdx.x] : 0.0;
    if (wid == 0) {
        #pragma unroll
        for (int o = 16; o; o >>= 1) v += __shfl_down_sync(0xffffffffu, v, o);
    }
    return v;
}

__global__ void zero_acc() { if (threadIdx.x < 4) g_acc[threadIdx.x] = 0.0; }

// ---------------------------------------------------------------------------
__global__ void prep_kernel(const float* __restrict__ igt,
                            const float* __restrict__ iout,
                            const float* __restrict__ mask) {
    double hole = 0.0, valid = 0.0;
    const int total = 2*3*HW0;
    int stride = gridDim.x * blockDim.x;
    for (int i = blockIdx.x*blockDim.x + threadIdx.x; i < total; i += stride) {
        int hw = i % HW0;
        int t  = i / HW0;
        int b  = t / 3;
        float g  = igt[i];
        float o  = iout[i];
        float mv = mask[b*HW0 + hw];
        float ad = fabsf(o - g);
        bool m = (mv != 0.0f);
        if (m) valid += (double)ad; else hole += (double)ad;
        float comp = m ? g : o;
        g_x0[i]          = o;
        g_x0[i + 6*HW0]  = g;
        g_x0[i + 12*HW0] = comp;
    }
    hole  = blockReduceSum(hole);
    __syncthreads();
    valid = blockReduceSum(valid);
    if (threadIdx.x == 0) {
        atomicAdd(&g_acc[0], hole);
        atomicAdd(&g_acc[1], valid);
    }
}

// ---------------------------------------------------------------------------
// Direct 3x3 conv + bias + ReLU. FFMA2 pairs over OUTPUT CHANNELS:
// lane pair = (co=2cp, co=2cp+1). Weight pairs pre-packed in smem at fill time
// (zero per-MAC packing ALU); pixel operand duplicated once per (ci,dy).
// Block 256 thr; tile 16h x 64w; 8 couts/block; thread: 4 px x 4 co-pairs.
// cp.async double buffer, 4 input channels per stage.
// ---------------------------------------------------------------------------
__global__ __launch_bounds__(256, 3)
void conv3x3_relu(const float* __restrict__ in, const float* __restrict__ wgt,
                  const float* __restrict__ bias, float* __restrict__ out,
                  int CIN, int COUT, int S)
{
    __shared__ __align__(16) float s_in[2][4][18*68];
    // [buf][ci][dy][cp][dx(0..2) + pad] : pk(w[2cp][k], w[2cp+1][k])
    __shared__ __align__(16) u64   s_w2[2][4][3][4][4];

    const int tid = threadIdx.x;
    const int tx = tid & 15, ty = tid >> 4;
    const int ncog = COUT >> 3;
    const int n = blockIdx.z / ncog, cog = blockIdx.z - n*ncog;
    const int w0 = blockIdx.x*64, h0 = blockIdx.y*16;

    const float* inb = in  + (size_t)n*CIN*S*S;
    const float* wb  = wgt + (size_t)(cog*8)*CIN*9;

    u64 acc[4][4];   // [co-pair][px]
    #pragma unroll
    for (int cp = 0; cp < 4; cp++) {
        acc[cp][0]=0ull; acc[cp][1]=0ull; acc[cp][2]=0ull; acc[cp][3]=0ull;
    }

    // ---- prologue: stage 0 fill ----
    {
        int nc0 = CIN < 4 ? CIN : 4;
        uint32_t sb = (uint32_t)__cvta_generic_to_shared(&s_in[0][0][0]);
        int tot = nc0*1188;
        for (int i = tid; i < tot; i += 256) {
            int ci = i/1188, rem = i - ci*1188;
            int r = rem/66, c = rem - r*66;
            int h = h0 + r - 1, w = w0 + c - 1;
            bool ok = ((unsigned)h < (unsigned)S) & ((unsigned)w < (unsigned)S);
            const float* g = ok ? inb + ((size_t)ci*S + h)*S + w : inb;
            cp4(sb + (uint32_t)((ci*18 + r)*68 + c)*4u, g, ok);
        }
        cp_commit();
        int nw = nc0*36;                       // (ci, cp, k) pairs, <=144
        if (tid < nw) {
            int cp = tid/(nc0*9), rem = tid - cp*nc0*9, ci = rem/9, k = rem - ci*9;
            int dy = k/3, dx = k - dy*3;
            float lo = __ldg(wb + (size_t)(2*cp  )*CIN*9 + (size_t)ci*9 + k);
            float hi = __ldg(wb + (size_t)(2*cp+1)*CIN*9 + (size_t)ci*9 + k);
            s_w2[0][ci][dy][cp][dx] = pk(lo, hi);
        }
    }

    int buf = 0;
    for (int c0 = 0; c0 < CIN; c0 += 4) {
        int c1 = c0 + 4;
        bool more = c1 < CIN;
        int nc1 = (CIN - c1) < 4 ? (CIN - c1) : 4;
        float wlo = 0.f, whi = 0.f;

        if (more) {
            uint32_t sb = (uint32_t)__cvta_generic_to_shared(&s_in[buf^1][0][0]);
            int tot = nc1*1188;
            for (int i = tid; i < tot; i += 256) {
                int ci = i/1188, rem = i - ci*1188;
                int r = rem/66, c = rem - r*66;
                int h = h0 + r - 1, w = w0 + c - 1;
                bool ok = ((unsigned)h < (unsigned)S) & ((unsigned)w < (unsigned)S);
                const float* g = ok ? inb + ((size_t)(c1+ci)*S + h)*S + w : inb;
                cp4(sb + (uint32_t)((ci*18 + r)*68 + c)*4u, g, ok);
            }
            cp_commit();
            int nw = nc1*36;
            if (tid < nw) {
                int cp = tid/(nc1*9), rem = tid - cp*nc1*9, ci = rem/9, k = rem - ci*9;
                wlo = __ldg(wb + (size_t)(2*cp  )*CIN*9 + (size_t)(c1+ci)*9 + k);
                whi = __ldg(wb + (size_t)(2*cp+1)*CIN*9 + (size_t)(c1+ci)*9 + k);
            }
        }
        if (more) cp_wait<1>(); else cp_wait<0>();
        __syncthreads();

        // ---- compute current stage ----
        int ncc = (CIN - c0) < 4 ? (CIN - c0) : 4;
        #pragma unroll
        for (int ci = 0; ci < 4; ci++) {
            if (ci < ncc) {
                #pragma unroll
                for (int dy = 0; dy < 3; dy++) {
                    const float* row = &s_in[buf][ci][(ty+dy)*68 + tx*4];
                    float4 q = *(const float4*)row;
                    float v4 = row[4], v5 = row[5];
                    u64 d0 = pk(q.x,q.x), d1 = pk(q.y,q.y), d2 = pk(q.z,q.z);
                    u64 d3 = pk(q.w,q.w), d4 = pk(v4,v4),   d5 = pk(v5,v5);
                    #pragma unroll
                    for (int cp = 0; cp < 4; cp++) {
                        const u64* wr = s_w2[buf][ci][dy][cp];
                        ulonglong2 w01 = *(const ulonglong2*)wr;
                        u64 w2v = wr[2];
                        // dx = 0
                        acc[cp][0] = fma2(d0, w01.x, acc[cp][0]);
                        acc[cp][1] = fma2(d1, w01.x, acc[cp][1]);
                        acc[cp][2] = fma2(d2, w01.x, acc[cp][2]);
                        acc[cp][3] = fma2(d3, w01.x, acc[cp][3]);
                        // dx = 1
                        acc[cp][0] = fma2(d1, w01.y, acc[cp][0]);
                        acc[cp][1] = fma2(d2, w01.y, acc[cp][1]);
                        acc[cp][2] = fma2(d3, w01.y, acc[cp][2]);
                        acc[cp][3] = fma2(d4, w01.y, acc[cp][3]);
                        // dx = 2
                        acc[cp][0] = fma2(d2, w2v, acc[cp][0]);
                        acc[cp][1] = fma2(d3, w2v, acc[cp][1]);
                        acc[cp][2] = fma2(d4, w2v, acc[cp][2]);
                        acc[cp][3] = fma2(d5, w2v, acc[cp][3]);
                    }
                }
            }
        }

        if (more) {
            int nw = nc1*36;
            if (tid < nw) {
                int cp = tid/(nc1*9), rem = tid - cp*nc1*9, ci = rem/9, k = rem - ci*9;
                int dy = k/3, dx = k - dy*3;
                s_w2[buf^1][ci][dy][cp][dx] = pk(wlo, whi);
            }
        }
        __syncthreads();
        buf ^= 1;
    }

    const int h = h0 + ty, w = w0 + tx*4;
    #pragma unroll
    for (int cp = 0; cp < 4; cp++) {
        float blo = bias[cog*8 + 2*cp], bhi = bias[cog*8 + 2*cp + 1];
        float2 a0 = upk(acc[cp][0]), a1 = upk(acc[cp][1]);
        float2 a2 = upk(acc[cp][2]), a3 = upk(acc[cp][3]);
        float4 olo, ohi;
        olo.x = fmaxf(a0.x + blo, 0.f); olo.y = fmaxf(a1.x + blo, 0.f);
        olo.z = fmaxf(a2.x + blo, 0.f); olo.w = fmaxf(a3.x + blo, 0.f);
        ohi.x = fmaxf(a0.y + bhi, 0.f); ohi.y = fmaxf(a1.y + bhi, 0.f);
        ohi.z = fmaxf(a2.y + bhi, 0.f); ohi.w = fmaxf(a3.y + bhi, 0.f);
        *(float4*)&out[((size_t)(n*COUT + cog*8 + 2*cp    )*S + h)*S + w] = olo;
        *(float4*)&out[((size_t)(n*COUT + cog*8 + 2*cp + 1)*S + h)*S + w] = ohi;
    }
}

// ---------------------------------------------------------------------------
__global__ void maxpool2(const float* __restrict__ in, float* __restrict__ out,
                         int C, int S) {
    const int So = S >> 1;
    const size_t total = (size_t)6*C*So*So;
    const size_t stride = (size_t)gridDim.x * blockDim.x;
    for (size_t i = blockIdx.x*(size_t)blockDim.x + threadIdx.x; i < total; i += stride) {
        int x = (int)(i % So);
        size_t t = i / So;
        int y = (int)(t % So);
        size_t ncc = t / So;
        const float* p = in + (ncc*S + 2*y)*S + 2*x;
        out[i] = fmaxf(fmaxf(p[0], p[1]), fmaxf(p[S], p[S+1]));
    }
}

// ---------------------------------------------------------------------------
__global__ void perc_kernel(const float* __restrict__ p, int C, int S) {
    const size_t per = (size_t)C*S*S;
    const size_t total = 2*per;
    const size_t stride = (size_t)gridDim.x * blockDim.x;
    double s = 0.0;
    for (size_t i = blockIdx.x*(size_t)blockDim.x + threadIdx.x; i < total; i += stride) {
        float po = p[i];
        float pg = p[i + 2*per];
        float pc = p[i + 4*per];
        s += (double)(fabsf(po-pg) + fabsf(pc-pg));
    }
    s = blockReduceSum(s);
    if (threadIdx.x == 0) atomicAdd(&g_acc[2], s);
}

// ---------------------------------------------------------------------------
// Style Gram-difference (FFMA2). 64x64 (w,v) tile per block, 4x4 micro.
// ---------------------------------------------------------------------------
__global__ __launch_bounds__(256, 2)
void style_kernel(const float* __restrict__ p, int C, int S, int va, double scale) {
    const int tid = threadIdx.x;
    const int tx = tid & 15, ty = tid >> 4;
    const int bc = blockIdx.z;
    const int b = bc / C, c = bc - b*C;
    const int wt = blockIdx.y * 64;
    const int vt = blockIdx.x * 64;
    const float* A = p + ((size_t)((va*2+b)*C + c)) * S * S;
    const float* G = p + ((size_t)((2   +b)*C + c)) * S * S;

    __shared__ __align__(16) float s_aw[32][64], s_av[32][64];
    __shared__ __align__(16) float s_gw[32][64], s_gv[32][64];

    u64 accA[4][2], accG[4][2];
    #pragma unroll
    for (int i = 0; i < 4; i++) {
        accA[i][0]=0ull; accA[i][1]=0ull; accG[i][0]=0ull; accG[i][1]=0ull;
    }

    for (int k0 = 0; k0 < S; k0 += 32) {
        __syncthreads();
        for (int i = tid; i < 32*64; i += 256) {
            int kk = i >> 6, col = i & 63;
            size_t row = (size_t)(k0+kk)*S;
            s_aw[kk][col] = A[row + wt + col];
            s_av[kk][col] = A[row + vt + col];
            s_gw[kk][col] = G[row + wt + col];
            s_gv[kk][col] = G[row + vt + col];
        }
        __syncthreads();
        #pragma unroll 4
        for (int kk = 0; kk < 32; kk++) {
            float4 aw4 = *(const float4*)&s_aw[kk][ty*4];
            float4 gw4 = *(const float4*)&s_gw[kk][ty*4];
            ulonglong2 av = *(const ulonglong2*)&s_av[kk][tx*4];
            ulonglong2 gv = *(const ulonglong2*)&s_gv[kk][tx*4];
            u64 aw[4] = {pk(aw4.x,aw4.x), pk(aw4.y,aw4.y), pk(aw4.z,aw4.z), pk(aw4.w,aw4.w)};
            u64 gw[4] = {pk(gw4.x,gw4.x), pk(gw4.y,gw4.y), pk(gw4.z,gw4.z), pk(gw4.w,gw4.w)};
            #pragma unroll
            for (int i = 0; i < 4; i++) {
                accA[i][0] = fma2(aw[i], av.x, accA[i][0]);
                accA[i][1] = fma2(aw[i], av.y, accA[i][1]);
                accG[i][0] = fma2(gw[i], gv.x, accG[i][0]);
                accG[i][1] = fma2(gw[i], gv.y, accG[i][1]);
            }
        }
    }
    double s = 0.0;
    #pragma unroll
    for (int i = 0; i < 4; i++) {
        #pragma unroll
        for (int j = 0; j < 2; j++) {
            float2 a = upk(accA[i][j]), g = upk(accG[i][j]);
            s += (double)fabsf(a.x - g.x) + (double)fabsf(a.y - g.y);
        }
    }
    s = blockReduceSum(s);
    if (threadIdx.x == 0) atomicAdd(&g_acc[3], scale * s);
}

// ---------------------------------------------------------------------------
__global__ void finish_kernel(float* __restrict__ out) {
    const double N    = 3.0*512.0*512.0*2.0;
    const double Nigt = 2.0*64.0*256.0*256.0;
    double t = 2.0*g_acc[0]/N
             +     g_acc[1]/N
             +     g_acc[2]/Nigt
             +     g_acc[3];
    out[0] = (float)t;
}

// ---------------------------------------------------------------------------
extern "C" void kernel_launch(void* const* d_in, const int* in_sizes, int n_in,
                              void* d_out, int out_size) {
    const float* igt  = (const float*)d_in[0];
    const float* iout = (const float*)d_in[1];
    const float* mask = (const float*)d_in[2];
    const float* w[7]; const float* bs[7];
    for (int i = 0; i < 7; i++) {
        w[i]  = (const float*)d_in[3 + 2*i];
        bs[i] = (const float*)d_in[4 + 2*i];
    }

    float *x0, *bufA, *bufB, *p1, *p2, *p3;
    cudaGetSymbolAddress((void**)&x0,   g_x0);
    cudaGetSymbolAddress((void**)&bufA, g_bufA);
    cudaGetSymbolAddress((void**)&bufB, g_bufB);
    cudaGetSymbolAddress((void**)&p1,   g_p1);
    cudaGetSymbolAddress((void**)&p2,   g_p2);
    cudaGetSymbolAddress((void**)&p3,   g_p3);

    zero_acc<<<1, 32>>>();
    prep_kernel<<<2048, 256>>>(igt, iout, mask);

    conv3x3_relu<<<dim3(8,32, 48), 256>>>(x0,   w[0], bs[0], bufA,   3,  64, 512);
    conv3x3_relu<<<dim3(8,32, 48), 256>>>(bufA, w[1], bs[1], bufB,  64,  64, 512);
    maxpool2<<<4096, 256>>>(bufB, p1, 64, 512);
    conv3x3_relu<<<dim3(4,16, 96), 256>>>(p1,   w[2], bs[2], bufA,  64, 128, 256);
    conv3x3_relu<<<dim3(4,16, 96), 256>>>(bufA, w[3], bs[3], bufB, 128, 128, 256);
    maxpool2<<<2048, 256>>>(bufB, p2, 128, 256);
    conv3x3_relu<<<dim3(2, 8,192), 256>>>(p2,   w[4], bs[4], bufA, 128, 256, 128);
    conv3x3_relu<<<dim3(2, 8,192), 256>>>(bufA, w[5], bs[5], bufB, 256, 256, 128);
    conv3x3_relu<<<dim3(2, 8,192), 256>>>(bufB, w[6], bs[6], bufA, 256, 256, 128);
    maxpool2<<<1024, 256>>>(bufA, p3, 256, 128);

    perc_kernel<<<2048, 256>>>(p1,  64, 256);
    perc_kernel<<<2048, 256>>>(p2, 128, 128);
    perc_kernel<<<1024, 256>>>(p3, 256,  64);

    const double s1 = 1.0/((double)64 *256*256)/( 64.0* 64.0);
    const double s2 = 1.0/((double)128*128*128)/(128.0*128.0);
    const double s3 = 1.0/((double)256* 64* 64)/(256.0*256.0);
    style_kernel<<<dim3(4,4,128), 256>>>(p1,  64, 256, 2, s1);
    style_kernel<<<dim3(4,4,128), 256>>>(p1,  64, 256, 0, s1);
    style_kernel<<<dim3(2,2,256), 256>>>(p2, 128, 128, 2, s2);
    style_kernel<<<dim3(2,2,256), 256>>>(p2, 128, 128, 0, s2);
    style_kernel<<<dim3(1,1,512), 256>>>(p3, 256,  64, 2, s3);
    style_kernel<<<dim3(1,1,512), 256>>>(p3, 256,  64, 0, s3);

    finish_kernel<<<1, 1>>>((float*)d_out);
}

// round 7
// speedup vs baseline: 1.6389x; 1.6389x over previous
#include <cuda_runtime.h>
#include <math.h>
#include <stdint.h>

// ---------------------------------------------------------------------------
// B=2, H=W=512. Three variants (iout, igt, icomp) -> 6 NCHW images.
// n = v*2 + b, v: 0=out, 1=gt, 2=comp.
// ---------------------------------------------------------------------------
#define HW0 (512*512)

__device__ float g_x0  [6*3*HW0];
__device__ float g_bufA[6*64*HW0];
__device__ float g_bufB[6*64*HW0];
__device__ float g_p1  [6*64*256*256];
__device__ float g_p2  [6*128*128*128];
__device__ float g_p3  [6*256*64*64];
__device__ double g_acc[4];   // 0:hole 1:valid 2:perc(raw) 3:style(scaled)

typedef unsigned long long u64;

// ---- packed f32x2 helpers --------------------------------------------------
__device__ __forceinline__ u64 pk(float lo, float hi) {
    u64 r; asm("mov.b64 %0,{%1,%2};" : "=l"(r) : "f"(lo), "f"(hi)); return r;
}
__device__ __forceinline__ float2 upk(u64 v) {
    float2 r; asm("mov.b64 {%0,%1},%2;" : "=f"(r.x), "=f"(r.y) : "l"(v)); return r;
}
__device__ __forceinline__ u64 fma2(u64 a, u64 b, u64 c) {
    u64 d; asm("fma.rn.f32x2 %0,%1,%2,%3;" : "=l"(d) : "l"(a), "l"(b), "l"(c)); return d;
}

// ---- cp.async helpers ------------------------------------------------------
__device__ __forceinline__ void cp4(uint32_t s, const float* g, bool ok) {
    asm volatile("cp.async.ca.shared.global [%0],[%1],4,%2;"
                 :: "r"(s), "l"(g), "r"(ok ? 4 : 0));
}
__device__ __forceinline__ void cp_commit() { asm volatile("cp.async.commit_group;"); }
template<int N> __device__ __forceinline__ void cp_wait() {
    asm volatile("cp.async.wait_group %0;" :: "n"(N));
}

// ---------------------------------------------------------------------------
__device__ __forceinline__ double blockReduceSum(double v) {
    __shared__ double s[32];
    int lane = threadIdx.x & 31, wid = threadIdx.x >> 5;
    #pragma unroll
    for (int o = 16; o; o >>= 1) v += __shfl_down_sync(0xffffffffu, v, o);
    if (lane == 0) s[wid] = v;
    __syncthreads();
    int nw = blockDim.x >> 5;
    v = (threadIdx.x < nw) ? s[threadIdx.x] : 0.0;
    if (wid == 0) {
        #pragma unroll
        for (int o = 16; o; o >>= 1) v += __shfl_down_sync(0xffffffffu, v, o);
    }
    return v;
}

__global__ void zero_acc() { if (threadIdx.x < 4) g_acc[threadIdx.x] = 0.0; }

// ---------------------------------------------------------------------------
__global__ void prep_kernel(const float* __restrict__ igt,
                            const float* __restrict__ iout,
                            const float* __restrict__ mask) {
    double hole = 0.0, valid = 0.0;
    const int total = 2*3*HW0;
    int stride = gridDim.x * blockDim.x;
    for (int i = blockIdx.x*blockDim.x + threadIdx.x; i < total; i += stride) {
        int hw = i % HW0;
        int t  = i / HW0;
        int b  = t / 3;
        float g  = igt[i];
        float o  = iout[i];
        float mv = mask[b*HW0 + hw];
        float ad = fabsf(o - g);
        bool m = (mv != 0.0f);
        if (m) valid += (double)ad; else hole += (double)ad;
        float comp = m ? g : o;
        g_x0[i]          = o;
        g_x0[i + 6*HW0]  = g;
        g_x0[i + 12*HW0] = comp;
    }
    hole  = blockReduceSum(hole);
    __syncthreads();
    valid = blockReduceSum(valid);
    if (threadIdx.x == 0) {
        atomicAdd(&g_acc[0], hole);
        atomicAdd(&g_acc[1], valid);
    }
}

// ---------------------------------------------------------------------------
// Direct 3x3 conv + bias + ReLU. FFMA2 pairs over OUTPUT CHANNELS:
// lane pair = (co=2cp, co=2cp+1). Weight pairs pre-packed in smem at fill time
// (zero per-MAC packing ALU); pixel operand duplicated once per (ci,dy).
// Block 256 thr; tile 16h x 64w; 8 couts/block; thread: 4 px x 4 co-pairs.
// cp.async double buffer, 4 input channels per stage.
// ---------------------------------------------------------------------------
__global__ __launch_bounds__(256, 3)
void conv3x3_relu(const float* __restrict__ in, const float* __restrict__ wgt,
                  const float* __restrict__ bias, float* __restrict__ out,
                  int CIN, int COUT, int S)
{
    __shared__ __align__(16) float s_in[2][4][18*68];
    // [buf][ci][dy][cp][dx(0..2) + pad] : pk(w[2cp][k], w[2cp+1][k])
    __shared__ __align__(16) u64   s_w2[2][4][3][4][4];

    const int tid = threadIdx.x;
    const int tx = tid & 15, ty = tid >> 4;
    const int ncog = COUT >> 3;
    const int n = blockIdx.z / ncog, cog = blockIdx.z - n*ncog;
    const int w0 = blockIdx.x*64, h0 = blockIdx.y*16;

    const float* inb = in  + (size_t)n*CIN*S*S;
    const float* wb  = wgt + (size_t)(cog*8)*CIN*9;

    u64 acc[4][4];   // [co-pair][px]
    #pragma unroll
    for (int cp = 0; cp < 4; cp++) {
        acc[cp][0]=0ull; acc[cp][1]=0ull; acc[cp][2]=0ull; acc[cp][3]=0ull;
    }

    // ---- prologue: stage 0 fill ----
    {
        int nc0 = CIN < 4 ? CIN : 4;
        uint32_t sb = (uint32_t)__cvta_generic_to_shared(&s_in[0][0][0]);
        int tot = nc0*1188;
        for (int i = tid; i < tot; i += 256) {
            int ci = i/1188, rem = i - ci*1188;
            int r = rem/66, c = rem - r*66;
            int h = h0 + r - 1, w = w0 + c - 1;
            bool ok = ((unsigned)h < (unsigned)S) & ((unsigned)w < (unsigned)S);
            const float* g = ok ? inb + ((size_t)ci*S + h)*S + w : inb;
            cp4(sb + (uint32_t)((ci*18 + r)*68 + c)*4u, g, ok);
        }
        cp_commit();
        int nw = nc0*36;                       // (ci, cp, k) pairs, <=144
        if (tid < nw) {
            int cp = tid/(nc0*9), rem = tid - cp*nc0*9, ci = rem/9, k = rem - ci*9;
            int dy = k/3, dx = k - dy*3;
            float lo = __ldg(wb + (size_t)(2*cp  )*CIN*9 + (size_t)ci*9 + k);
            float hi = __ldg(wb + (size_t)(2*cp+1)*CIN*9 + (size_t)ci*9 + k);
            s_w2[0][ci][dy][cp][dx] = pk(lo, hi);
        }
    }

    int buf = 0;
    for (int c0 = 0; c0 < CIN; c0 += 4) {
        int c1 = c0 + 4;
        bool more = c1 < CIN;
        int nc1 = (CIN - c1) < 4 ? (CIN - c1) : 4;
        float wlo = 0.f, whi = 0.f;

        if (more) {
            uint32_t sb = (uint32_t)__cvta_generic_to_shared(&s_in[buf^1][0][0]);
            int tot = nc1*1188;
            for (int i = tid; i < tot; i += 256) {
                int ci = i/1188, rem = i - ci*1188;
                int r = rem/66, c = rem - r*66;
                int h = h0 + r - 1, w = w0 + c - 1;
                bool ok = ((unsigned)h < (unsigned)S) & ((unsigned)w < (unsigned)S);
                const float* g = ok ? inb + ((size_t)(c1+ci)*S + h)*S + w : inb;
                cp4(sb + (uint32_t)((ci*18 + r)*68 + c)*4u, g, ok);
            }
            cp_commit();
            int nw = nc1*36;
            if (tid < nw) {
                int cp = tid/(nc1*9), rem = tid - cp*nc1*9, ci = rem/9, k = rem - ci*9;
                wlo = __ldg(wb + (size_t)(2*cp  )*CIN*9 + (size_t)(c1+ci)*9 + k);
                whi = __ldg(wb + (size_t)(2*cp+1)*CIN*9 + (size_t)(c1+ci)*9 + k);
            }
        }
        if (more) cp_wait<1>(); else cp_wait<0>();
        __syncthreads();

        // ---- compute current stage ----
        int ncc = (CIN - c0) < 4 ? (CIN - c0) : 4;
        #pragma unroll
        for (int ci = 0; ci < 4; ci++) {
            if (ci < ncc) {
                #pragma unroll
                for (int dy = 0; dy < 3; dy++) {
                    const float* row = &s_in[buf][ci][(ty+dy)*68 + tx*4];
                    float4 q = *(const float4*)row;
                    float v4 = row[4], v5 = row[5];
                    u64 d0 = pk(q.x,q.x), d1 = pk(q.y,q.y), d2 = pk(q.z,q.z);
                    u64 d3 = pk(q.w,q.w), d4 = pk(v4,v4),   d5 = pk(v5,v5);
                    #pragma unroll
                    for (int cp = 0; cp < 4; cp++) {
                        const u64* wr = s_w2[buf][ci][dy][cp];
                        ulonglong2 w01 = *(const ulonglong2*)wr;
                        u64 w2v = wr[2];
                        // dx = 0
                        acc[cp][0] = fma2(d0, w01.x, acc[cp][0]);
                        acc[cp][1] = fma2(d1, w01.x, acc[cp][1]);
                        acc[cp][2] = fma2(d2, w01.x, acc[cp][2]);
                        acc[cp][3] = fma2(d3, w01.x, acc[cp][3]);
                        // dx = 1
                        acc[cp][0] = fma2(d1, w01.y, acc[cp][0]);
                        acc[cp][1] = fma2(d2, w01.y, acc[cp][1]);
                        acc[cp][2] = fma2(d3, w01.y, acc[cp][2]);
                        acc[cp][3] = fma2(d4, w01.y, acc[cp][3]);
                        // dx = 2
                        acc[cp][0] = fma2(d2, w2v, acc[cp][0]);
                        acc[cp][1] = fma2(d3, w2v, acc[cp][1]);
                        acc[cp][2] = fma2(d4, w2v, acc[cp][2]);
                        acc[cp][3] = fma2(d5, w2v, acc[cp][3]);
                    }
                }
            }
        }

        if (more) {
            int nw = nc1*36;
            if (tid < nw) {
                int cp = tid/(nc1*9), rem = tid - cp*nc1*9, ci = rem/9, k = rem - ci*9;
                int dy = k/3, dx = k - dy*3;
                s_w2[buf^1][ci][dy][cp][dx] = pk(wlo, whi);
            }
        }
        __syncthreads();
        buf ^= 1;
    }

    const int h = h0 + ty, w = w0 + tx*4;
    #pragma unroll
    for (int cp = 0; cp < 4; cp++) {
        float blo = bias[cog*8 + 2*cp], bhi = bias[cog*8 + 2*cp + 1];
        float2 a0 = upk(acc[cp][0]), a1 = upk(acc[cp][1]);
        float2 a2 = upk(acc[cp][2]), a3 = upk(acc[cp][3]);
        float4 olo, ohi;
        olo.x = fmaxf(a0.x + blo, 0.f); olo.y = fmaxf(a1.x + blo, 0.f);
        olo.z = fmaxf(a2.x + blo, 0.f); olo.w = fmaxf(a3.x + blo, 0.f);
        ohi.x = fmaxf(a0.y + bhi, 0.f); ohi.y = fmaxf(a1.y + bhi, 0.f);
        ohi.z = fmaxf(a2.y + bhi, 0.f); ohi.w = fmaxf(a3.y + bhi, 0.f);
        *(float4*)&out[((size_t)(n*COUT + cog*8 + 2*cp    )*S + h)*S + w] = olo;
        *(float4*)&out[((size_t)(n*COUT + cog*8 + 2*cp + 1)*S + h)*S + w] = ohi;
    }
}

// ---------------------------------------------------------------------------
__global__ void maxpool2(const float* __restrict__ in, float* __restrict__ out,
                         int C, int S) {
    const int So = S >> 1;
    const size_t total = (size_t)6*C*So*So;
    const size_t stride = (size_t)gridDim.x * blockDim.x;
    for (size_t i = blockIdx.x*(size_t)blockDim.x + threadIdx.x; i < total; i += stride) {
        int x = (int)(i % So);
        size_t t = i / So;
        int y = (int)(t % So);
        size_t ncc = t / So;
        const float* p = in + (ncc*S + 2*y)*S + 2*x;
        out[i] = fmaxf(fmaxf(p[0], p[1]), fmaxf(p[S], p[S+1]));
    }
}

// ---------------------------------------------------------------------------
__global__ void perc_kernel(const float* __restrict__ p, int C, int S) {
    const size_t per = (size_t)C*S*S;
    const size_t total = 2*per;
    const size_t stride = (size_t)gridDim.x * blockDim.x;
    double s = 0.0;
    for (size_t i = blockIdx.x*(size_t)blockDim.x + threadIdx.x; i < total; i += stride) {
        float po = p[i];
        float pg = p[i + 2*per];
        float pc = p[i + 4*per];
        s += (double)(fabsf(po-pg) + fabsf(pc-pg));
    }
    s = blockReduceSum(s);
    if (threadIdx.x == 0) atomicAdd(&g_acc[2], s);
}

// ---------------------------------------------------------------------------
// Style Gram-difference (FFMA2). 64x64 (w,v) tile per block, 4x4 micro.
// ---------------------------------------------------------------------------
__global__ __launch_bounds__(256, 2)
void style_kernel(const float* __restrict__ p, int C, int S, int va, double scale) {
    const int tid = threadIdx.x;
    const int tx = tid & 15, ty = tid >> 4;
    const int bc = blockIdx.z;
    const int b = bc / C, c = bc - b*C;
    const int wt = blockIdx.y * 64;
    const int vt = blockIdx.x * 64;
    const float* A = p + ((size_t)((va*2+b)*C + c)) * S * S;
    const float* G = p + ((size_t)((2   +b)*C + c)) * S * S;

    __shared__ __align__(16) float s_aw[32][64], s_av[32][64];
    __shared__ __align__(16) float s_gw[32][64], s_gv[32][64];

    u64 accA[4][2], accG[4][2];
    #pragma unroll
    for (int i = 0; i < 4; i++) {
        accA[i][0]=0ull; accA[i][1]=0ull; accG[i][0]=0ull; accG[i][1]=0ull;
    }

    for (int k0 = 0; k0 < S; k0 += 32) {
        __syncthreads();
        for (int i = tid; i < 32*64; i += 256) {
            int kk = i >> 6, col = i & 63;
            size_t row = (size_t)(k0+kk)*S;
            s_aw[kk][col] = A[row + wt + col];
            s_av[kk][col] = A[row + vt + col];
            s_gw[kk][col] = G[row + wt + col];
            s_gv[kk][col] = G[row + vt + col];
        }
        __syncthreads();
        #pragma unroll 4
        for (int kk = 0; kk < 32; kk++) {
            float4 aw4 = *(const float4*)&s_aw[kk][ty*4];
            float4 gw4 = *(const float4*)&s_gw[kk][ty*4];
            ulonglong2 av = *(const ulonglong2*)&s_av[kk][tx*4];
            ulonglong2 gv = *(const ulonglong2*)&s_gv[kk][tx*4];
            u64 aw[4] = {pk(aw4.x,aw4.x), pk(aw4.y,aw4.y), pk(aw4.z,aw4.z), pk(aw4.w,aw4.w)};
            u64 gw[4] = {pk(gw4.x,gw4.x), pk(gw4.y,gw4.y), pk(gw4.z,gw4.z), pk(gw4.w,gw4.w)};
            #pragma unroll
            for (int i = 0; i < 4; i++) {
                accA[i][0] = fma2(aw[i], av.x, accA[i][0]);
                accA[i][1] = fma2(aw[i], av.y, accA[i][1]);
                accG[i][0] = fma2(gw[i], gv.x, accG[i][0]);
                accG[i][1] = fma2(gw[i], gv.y, accG[i][1]);
            }
        }
    }
    double s = 0.0;
    #pragma unroll
    for (int i = 0; i < 4; i++) {
        #pragma unroll
        for (int j = 0; j < 2; j++) {
            float2 a = upk(accA[i][j]), g = upk(accG[i][j]);
            s += (double)fabsf(a.x - g.x) + (double)fabsf(a.y - g.y);
        }
    }
    s = blockReduceSum(s);
    if (threadIdx.x == 0) atomicAdd(&g_acc[3], scale * s);
}

// ---------------------------------------------------------------------------
__global__ void finish_kernel(float* __restrict__ out) {
    const double N    = 3.0*512.0*512.0*2.0;
    const double Nigt = 2.0*64.0*256.0*256.0;
    double t = 2.0*g_acc[0]/N
             +     g_acc[1]/N
             +     g_acc[2]/Nigt
             +     g_acc[3];
    out[0] = (float)t;
}

// ---------------------------------------------------------------------------
extern "C" void kernel_launch(void* const* d_in, const int* in_sizes, int n_in,
                              void* d_out, int out_size) {
    const float* igt  = (const float*)d_in[0];
    const float* iout = (const float*)d_in[1];
    const float* mask = (const float*)d_in[2];
    const float* w[7]; const float* bs[7];
    for (int i = 0; i < 7; i++) {
        w[i]  = (const float*)d_in[3 + 2*i];
        bs[i] = (const float*)d_in[4 + 2*i];
    }

    float *x0, *bufA, *bufB, *p1, *p2, *p3;
    cudaGetSymbolAddress((void**)&x0,   g_x0);
    cudaGetSymbolAddress((void**)&bufA, g_bufA);
    cudaGetSymbolAddress((void**)&bufB, g_bufB);
    cudaGetSymbolAddress((void**)&p1,   g_p1);
    cudaGetSymbolAddress((void**)&p2,   g_p2);
    cudaGetSymbolAddress((void**)&p3,   g_p3);

    zero_acc<<<1, 32>>>();
    prep_kernel<<<2048, 256>>>(igt, iout, mask);

    conv3x3_relu<<<dim3(8,32, 48), 256>>>(x0,   w[0], bs[0], bufA,   3,  64, 512);
    conv3x3_relu<<<dim3(8,32, 48), 256>>>(bufA, w[1], bs[1], bufB,  64,  64, 512);
    maxpool2<<<4096, 256>>>(bufB, p1, 64, 512);
    conv3x3_relu<<<dim3(4,16, 96), 256>>>(p1,   w[2], bs[2], bufA,  64, 128, 256);
    conv3x3_relu<<<dim3(4,16, 96), 256>>>(bufA, w[3], bs[3], bufB, 128, 128, 256);
    maxpool2<<<2048, 256>>>(bufB, p2, 128, 256);
    conv3x3_relu<<<dim3(2, 8,192), 256>>>(p2,   w[4], bs[4], bufA, 128, 256, 128);
    conv3x3_relu<<<dim3(2, 8,192), 256>>>(bufA, w[5], bs[5], bufB, 256, 256, 128);
    conv3x3_relu<<<dim3(2, 8,192), 256>>>(bufB, w[6], bs[6], bufA, 256, 256, 128);
    maxpool2<<<1024, 256>>>(bufA, p3, 256, 128);

    perc_kernel<<<2048, 256>>>(p1,  64, 256);
    perc_kernel<<<2048, 256>>>(p2, 128, 128);
    perc_kernel<<<1024, 256>>>(p3, 256,  64);

    const double s1 = 1.0/((double)64 *256*256)/( 64.0* 64.0);
    const double s2 = 1.0/((double)128*128*128)/(128.0*128.0);
    const double s3 = 1.0/((double)256* 64* 64)/(256.0*256.0);
    style_kernel<<<dim3(4,4,128), 256>>>(p1,  64, 256, 2, s1);
    style_kernel<<<dim3(4,4,128), 256>>>(p1,  64, 256, 0, s1);
    style_kernel<<<dim3(2,2,256), 256>>>(p2, 128, 128, 2, s2);
    style_kernel<<<dim3(2,2,256), 256>>>(p2, 128, 128, 0, s2);
    style_kernel<<<dim3(1,1,512), 256>>>(p3, 256,  64, 2, s3);
    style_kernel<<<dim3(1,1,512), 256>>>(p3, 256,  64, 0, s3);

    finish_kernel<<<1, 1>>>((float*)d_out);
}

// round 11
// speedup vs baseline: 4.5505x; 2.7765x over previous
#include <cuda_runtime.h>
#include <cuda_bf16.h>
#include <math.h>
#include <stdint.h>

#define HW0 (512*512)
typedef unsigned long long u64;
typedef __nv_bfloat16 bf16;

__device__ float g_x0  [6*3*HW0];
__device__ float g_bufA[6*64*HW0];
__device__ float g_p1  [6*64*256*256];
__device__ float g_p2  [6*128*128*128];
__device__ float g_p3  [6*256*64*64];
__device__ double g_acc[4];
__device__ bf16 g_hA[100663296];
__device__ bf16 g_lA[100663296];
__device__ bf16 g_hB[100663296];
__device__ bf16 g_lB[100663296];
__device__ bf16 g_wHi[1732608];
__device__ bf16 g_wLo[1732608];

__device__ __forceinline__ u64 pk(float lo, float hi) {
    u64 r; asm("mov.b64 %0,{%1,%2};" : "=l"(r) : "f"(lo), "f"(hi)); return r;
}
__device__ __forceinline__ float2 upk(u64 v) {
    float2 r; asm("mov.b64 {%0,%1},%2;" : "=f"(r.x), "=f"(r.y) : "l"(v)); return r;
}
__device__ __forceinline__ u64 fma2(u64 a, u64 b, u64 c) {
    u64 d; asm("fma.rn.f32x2 %0,%1,%2,%3;" : "=l"(d) : "l"(a), "l"(b), "l"(c)); return d;
}
__device__ __forceinline__ void cp4(uint32_t s, const float* g, bool ok) {
    asm volatile("cp.async.ca.shared.global [%0],[%1],4,%2;" :: "r"(s), "l"(g), "r"(ok?4:0));
}
__device__ __forceinline__ void cp16(uint32_t s, const void* g, bool ok) {
    asm volatile("cp.async.cg.shared.global [%0],[%1],16,%2;" :: "r"(s), "l"(g), "r"(ok?16:0));
}
__device__ __forceinline__ void cp_commit() { asm volatile("cp.async.commit_group;"); }
template<int N> __device__ __forceinline__ void cp_wait() {
    asm volatile("cp.async.wait_group %0;" :: "n"(N));
}
__device__ __forceinline__ void ldsm4(uint32_t* r, uint32_t a) {
    asm volatile("ldmatrix.sync.aligned.m8n8.x4.shared.b16 {%0,%1,%2,%3},[%4];"
        : "=r"(r[0]), "=r"(r[1]), "=r"(r[2]), "=r"(r[3]) : "r"(a));
}
__device__ __forceinline__ void mma16816(float* c, const uint32_t* a, const uint32_t* b) {
    asm volatile("mma.sync.aligned.m16n8k16.row.col.f32.bf16.bf16.f32 "
        "{%0,%1,%2,%3},{%4,%5,%6,%7},{%8,%9},{%0,%1,%2,%3};"
        : "+f"(c[0]), "+f"(c[1]), "+f"(c[2]), "+f"(c[3])
        : "r"(a[0]), "r"(a[1]), "r"(a[2]), "r"(a[3]), "r"(b[0]), "r"(b[1]));
}

__device__ __forceinline__ double blockReduceSum(double v) {
    __shared__ double s[32];
    int lane = threadIdx.x & 31, wid = threadIdx.x >> 5;
    #pragma unroll
    for (int o = 16; o; o >>= 1) v += __shfl_down_sync(0xffffffffu, v, o);
    if (lane == 0) s[wid] = v;
    __syncthreads();
    int nw = blockDim.x >> 5;
    v = (threadIdx.x < nw) ? s[threadIdx.x] : 0.0;
    if (wid == 0) {
        #pragma unroll
        for (int o = 16; o; o >>= 1) v += __shfl_down_sync(0xffffffffu, v, o);
    }
    return v;
}

__global__ void zero_acc() { if (threadIdx.x < 4) g_acc[threadIdx.x] = 0.0; }

__global__ void prep_kernel(const float* __restrict__ igt, const float* __restrict__ iout,
                            const float* __restrict__ mask) {
    double hole = 0.0, valid = 0.0;
    const int total = 2*3*HW0;
    int stride = gridDim.x * blockDim.x;
    for (int i = blockIdx.x*blockDim.x + threadIdx.x; i < total; i += stride) {
        int hw = i % HW0, t = i / HW0, b = t / 3;
        float g = igt[i], o = iout[i];
        float mv = mask[b*HW0 + hw];
        float ad = fabsf(o - g);
        bool m = (mv != 0.0f);
        if (m) valid += (double)ad; else hole += (double)ad;
        g_x0[i] = o; g_x0[i + 6*HW0] = g; g_x0[i + 12*HW0] = m ? g : o;
    }
    hole = blockReduceSum(hole);
    __syncthreads();
    valid = blockReduceSum(valid);
    if (threadIdx.x == 0) { atomicAdd(&g_acc[0], hole); atomicAdd(&g_acc[1], valid); }
}

// Weight prepack: fp32 OIHW -> hi/lo bf16 blocks [k9][cog][chunk]: N rows x 64 ci
__global__ void prep_w(const float* __restrict__ w, int CIN, int COUT, int N, int base) {
    int ncog = COUT / N, chunks = CIN >> 6;
    int total = 9*COUT*CIN;
    int stride = gridDim.x*blockDim.x;
    for (int i = blockIdx.x*blockDim.x + threadIdx.x; i < total; i += stride) {
        int inner = i % (N*64), blk = i / (N*64);
        int chunk = blk % chunks; int r1 = blk / chunks;
        int cog = r1 % ncog; int k9 = r1 / ncog;
        int row = inner >> 6, ci = inner & 63;
        int co = cog*N + row, c = chunk*64 + ci;
        int dy = k9/3, dx = k9 - dy*3;
        float v = w[((size_t)(co*CIN + c)*3 + dy)*3 + dx];
        bf16 hi = __float2bfloat16(v);
        bf16 lo = __float2bfloat16(v - __bfloat162float(hi));
        size_t dst = (size_t)base + (size_t)blk*(N*64) + inner;
        g_wHi[dst] = hi; g_wLo[dst] = lo;
    }
}

// L0 direct FFMA2 conv (CIN=3), fp32 NCHW out
__global__ __launch_bounds__(256, 3)
void conv_l0(const float* __restrict__ in, const float* __restrict__ wgt,
             const float* __restrict__ bias, float* __restrict__ out, int S)
{
    const int CIN = 3, COUT = 64;
    __shared__ __align__(16) float s_in[4][18*68];
    __shared__ __align__(16) u64 s_w2[4][3][4][4];
    const int tid = threadIdx.x;
    const int tx = tid & 15, ty = tid >> 4;
    const int n = blockIdx.z >> 3, cog = blockIdx.z & 7;
    const int w0 = blockIdx.x*64, h0 = blockIdx.y*16;
    const float* inb = in + (size_t)n*CIN*S*S;
    const float* wb = wgt + (size_t)(cog*8)*CIN*9;

    u64 acc[4][4];
    #pragma unroll
    for (int cp = 0; cp < 4; cp++) { acc[cp][0]=0; acc[cp][1]=0; acc[cp][2]=0; acc[cp][3]=0; }

    uint32_t sb = (uint32_t)__cvta_generic_to_shared(&s_in[0][0]);
    for (int i = tid; i < 3*1188; i += 256) {
        int ci = i/1188, rem = i - ci*1188;
        int r = rem/66, c = rem - r*66;
        int h = h0 + r - 1, w = w0 + c - 1;
        bool ok = ((unsigned)h < (unsigned)S) & ((unsigned)w < (unsigned)S);
        const float* g = ok ? inb + ((size_t)ci*S + h)*S + w : inb;
        cp4(sb + (uint32_t)((ci*18 + r)*68 + c)*4u, g, ok);
    }
    cp_commit();
    if (tid < 108) {
        int cp = tid/27, rem = tid - cp*27, ci = rem/9, k = rem - ci*9;
        int dy = k/3, dx = k - dy*3;
        float lo = __ldg(wb + (size_t)(2*cp)*27 + (size_t)ci*9 + k);
        float hi = __ldg(wb + (size_t)(2*cp+1)*27 + (size_t)ci*9 + k);
        s_w2[ci][dy][cp][dx] = pk(lo, hi);
    }
    cp_wait<0>();
    __syncthreads();

    #pragma unroll
    for (int ci = 0; ci < 3; ci++) {
        #pragma unroll
        for (int dy = 0; dy < 3; dy++) {
            const float* row = &s_in[ci][(ty+dy)*68 + tx*4];
            float4 q = *(const float4*)row;
            float v4 = row[4], v5 = row[5];
            u64 d0=pk(q.x,q.x), d1=pk(q.y,q.y), d2=pk(q.z,q.z), d3=pk(q.w,q.w), d4=pk(v4,v4), d5=pk(v5,v5);
            #pragma unroll
            for (int cp = 0; cp < 4; cp++) {
                const u64* wr = s_w2[ci][dy][cp];
                ulonglong2 w01 = *(const ulonglong2*)wr;
                u64 w2v = wr[2];
                acc[cp][0]=fma2(d0,w01.x,acc[cp][0]); acc[cp][1]=fma2(d1,w01.x,acc[cp][1]);
                acc[cp][2]=fma2(d2,w01.x,acc[cp][2]); acc[cp][3]=fma2(d3,w01.x,acc[cp][3]);
                acc[cp][0]=fma2(d1,w01.y,acc[cp][0]); acc[cp][1]=fma2(d2,w01.y,acc[cp][1]);
                acc[cp][2]=fma2(d3,w01.y,acc[cp][2]); acc[cp][3]=fma2(d4,w01.y,acc[cp][3]);
                acc[cp][0]=fma2(d2,w2v,acc[cp][0]);  acc[cp][1]=fma2(d3,w2v,acc[cp][1]);
                acc[cp][2]=fma2(d4,w2v,acc[cp][2]);  acc[cp][3]=fma2(d5,w2v,acc[cp][3]);
            }
        }
    }
    const int h = h0 + ty, w = w0 + tx*4;
    #pragma unroll
    for (int cp = 0; cp < 4; cp++) {
        float blo = bias[cog*8+2*cp], bhi = bias[cog*8+2*cp+1];
        float2 a0=upk(acc[cp][0]), a1=upk(acc[cp][1]), a2=upk(acc[cp][2]), a3=upk(acc[cp][3]);
        float4 ol, oh;
        ol.x=fmaxf(a0.x+blo,0.f); ol.y=fmaxf(a1.x+blo,0.f); ol.z=fmaxf(a2.x+blo,0.f); ol.w=fmaxf(a3.x+blo,0.f);
        oh.x=fmaxf(a0.y+bhi,0.f); oh.y=fmaxf(a1.y+bhi,0.f); oh.z=fmaxf(a2.y+bhi,0.f); oh.w=fmaxf(a3.y+bhi,0.f);
        *(float4*)&out[((size_t)(n*COUT+cog*8+2*cp  )*S+h)*S+w] = ol;
        *(float4*)&out[((size_t)(n*COUT+cog*8+2*cp+1)*S+h)*S+w] = oh;
    }
}

// NCHW fp32 (C=64,S=512) -> NHWC hi/lo bf16
__global__ void to_nhwc(const float* __restrict__ in, bf16* __restrict__ ohi, bf16* __restrict__ olo) {
    __shared__ float t[64][33];
    int tid = threadIdx.x;
    int n = blockIdx.y;
    int hw0 = blockIdx.x*32;
    for (int i = tid; i < 64*32; i += 256) {
        int c = i >> 5, j = i & 31;
        t[c][j] = in[((size_t)(n*64+c) << 18) + hw0 + j];
    }
    __syncthreads();
    for (int i = tid; i < 32*64; i += 256) {
        int j = i >> 6, c = i & 63;
        float v = t[c][j];
        bf16 h = __float2bfloat16(v);
        size_t o = (((size_t)n << 18) + hw0 + j)*64 + c;
        ohi[o] = h;
        olo[o] = __float2bfloat16(v - __bfloat162float(h));
    }
}

// ---------------------------------------------------------------------------
// mma.sync implicit-GEMM conv (baseline PTX HMMA path; tcgen05 unavailable on
// this toolchain's sm_103 target). M=128 pixels, N=NT couts, K=64 chunks x 9
// shifts. fp32 via bf16 hi/lo: D += Ahi*Bhi + Ahi*Blo + Alo*Bhi.
// SMEM rows padded to 144B (conflict-free ldmatrix). cp.async double buffer.
// ---------------------------------------------------------------------------
template<int NT>
__global__ __launch_bounds__(256, 1)
void conv_mma(const bf16* __restrict__ ihi, const bf16* __restrict__ ilo,
              const float* __restrict__ bias, bf16* __restrict__ ohi, bf16* __restrict__ olo,
              int CIN, int COUT, int S, int wbase)
{
    constexpr int WARPS_M = (NT == 128) ? 2 : 4;
    constexpr int MT = (NT == 128) ? 4 : 2;     // m16 tiles per warp
    constexpr int MW = MT*16;                    // rows per warp
    constexpr uint32_t ASZ = 128*144u;           // one A term tile
    constexpr uint32_t BSZ = (uint32_t)NT*144u;  // one B term tile
    constexpr uint32_t BUFSZ = 2*ASZ + 2*BSZ;

    extern __shared__ __align__(16) char dsm[];
    const int tid = threadIdx.x;
    const int wid = tid >> 5, lane = tid & 31;
    const int wm = wid % WARPS_M, wn = wid / WARPS_M;
    const int ncog = COUT / NT;
    const int chunks = CIN >> 6;
    const int n = blockIdx.z / ncog, cog = blockIdx.z - n*ncog;
    const int w0 = blockIdx.x << 7;
    const int h = blockIdx.y;

    uint32_t sbase = ((uint32_t)__cvta_generic_to_shared(dsm) + 127u) & ~127u;
    const int NS = 9*chunks;

    float acc[MT][4][4];
    #pragma unroll
    for (int mt = 0; mt < MT; mt++)
        #pragma unroll
        for (int nt = 0; nt < 4; nt++)
            { acc[mt][nt][0]=0.f; acc[mt][nt][1]=0.f; acc[mt][nt][2]=0.f; acc[mt][nt][3]=0.f; }

    const uint32_t rA = (uint32_t)(lane & 15)*144u + (uint32_t)(lane >> 4)*16u;
    const uint32_t rB = (uint32_t)((lane & 7) + ((lane >> 4) << 3))*144u
                      + (uint32_t)((lane >> 3) & 1)*16u;

    auto build = [&](int st, int fb) {
        uint32_t bo = sbase + (uint32_t)fb*BUFSZ;
        int shift = st / chunks, chunk = st - shift*chunks;
        int dy = shift/3, dx = shift - dy*3;
        int hh = h + dy - 1;
        bool hok = ((unsigned)hh < (unsigned)S);
        int hcl = hok ? hh : 0;
        // A: 128 rows x 64 bf16 (8 x 16B segs), terms hi/lo
        for (int i = tid; i < 2048; i += 256) {
            int term = i >> 10, r = (i >> 3) & 127, seg = i & 7;
            int wp = w0 + r + dx - 1;
            bool ok = hok && ((unsigned)wp < (unsigned)S);
            int wcl = ok ? wp : 0;
            const bf16* src = term ? ilo : ihi;
            const void* g = src + ((size_t)(n*S + hcl)*S + wcl)*CIN + chunk*64 + seg*8;
            cp16(bo + (uint32_t)term*ASZ + (uint32_t)r*144u + (uint32_t)seg*16u, g, ok);
        }
        // B: NT rows x 64 bf16, terms hi/lo (prepacked contiguous blocks)
        size_t wblk = (size_t)wbase + (size_t)((shift*ncog + cog)*chunks + chunk)*((size_t)NT*64);
        constexpr int bq = NT*8;
        for (int i = tid; i < 2*bq; i += 256) {
            int term = (i >= bq);
            int q = term ? i - bq : i;
            const bf16* src = term ? g_wLo : g_wHi;
            cp16(bo + 2*ASZ + (uint32_t)term*BSZ + (uint32_t)(q >> 3)*144u + (uint32_t)(q & 7)*16u,
                 src + wblk + (size_t)q*8, true);
        }
        cp_commit();
    };

    auto compute = [&](int fb) {
        uint32_t bo = sbase + (uint32_t)fb*BUFSZ;
        #pragma unroll
        for (int term = 0; term < 3; term++) {
            uint32_t Ab = bo + ((term == 2) ? ASZ : 0u);
            uint32_t Bb = bo + 2*ASZ + ((term == 1) ? BSZ : 0u);
            #pragma unroll
            for (int k16 = 0; k16 < 4; k16++) {
                uint32_t bf[2][4], af[MT][4];
                #pragma unroll
                for (int p = 0; p < 2; p++)
                    ldsm4(bf[p], Bb + (uint32_t)(wn*32 + p*16)*144u + rB + (uint32_t)k16*32u);
                #pragma unroll
                for (int mt = 0; mt < MT; mt++)
                    ldsm4(af[mt], Ab + (uint32_t)(wm*MW + mt*16)*144u + rA + (uint32_t)k16*32u);
                #pragma unroll
                for (int mt = 0; mt < MT; mt++)
                    #pragma unroll
                    for (int nt = 0; nt < 4; nt++)
                        mma16816(acc[mt][nt], af[mt], &bf[nt >> 1][(nt & 1)*2]);
            }
        }
    };

    build(0, 0);
    for (int st = 0; st < NS; st++) {
        int fb = st & 1;
        if (st + 1 < NS) { build(st + 1, fb ^ 1); cp_wait<1>(); }
        else             { cp_wait<0>(); }
        __syncthreads();
        compute(fb);
        __syncthreads();
    }

    // Epilogue: bias + ReLU, NHWC hi/lo
    const float* bp = bias + cog*NT + wn*32;
    #pragma unroll
    for (int mt = 0; mt < MT; mt++) {
        int r0 = wm*MW + mt*16 + (lane >> 2);
        #pragma unroll
        for (int half = 0; half < 2; half++) {
            int px = w0 + r0 + half*8;
            size_t ob = ((size_t)(n*S + h)*S + px)*COUT + (size_t)(cog*NT + wn*32);
            #pragma unroll
            for (int nt = 0; nt < 4; nt++) {
                int co = nt*8 + (lane & 3)*2;
                float v0 = fmaxf(acc[mt][nt][half*2]   + __ldg(bp + co),     0.f);
                float v1 = fmaxf(acc[mt][nt][half*2+1] + __ldg(bp + co + 1), 0.f);
                bf16 h0 = __float2bfloat16(v0);
                bf16 h1 = __float2bfloat16(v1);
                __nv_bfloat162 hp, lp;
                hp.x = h0; hp.y = h1;
                lp.x = __float2bfloat16(v0 - __bfloat162float(h0));
                lp.y = __float2bfloat16(v1 - __bfloat162float(h1));
                *(__nv_bfloat162*)(ohi + ob + co) = hp;
                *(__nv_bfloat162*)(olo + ob + co) = lp;
            }
        }
    }
}

// Pool: NHWC hi/lo -> NCHW fp32 + optional NHWC hi/lo
__global__ void pool_mma(const bf16* __restrict__ ihi, const bf16* __restrict__ ilo,
                         float* __restrict__ pout, bf16* __restrict__ ohi, bf16* __restrict__ olo,
                         int C, int S, int writeN)
{
    const int So = S >> 1;
    const size_t total = (size_t)6*So*So*C;
    const size_t stride = (size_t)gridDim.x*blockDim.x;
    for (size_t i = blockIdx.x*(size_t)blockDim.x + threadIdx.x; i < total; i += stride) {
        int c = (int)(i % C);
        size_t t = i / C;
        int xo = (int)(t % So); t /= So;
        int yo = (int)(t % So);
        int n = (int)(t / So);
        size_t b00 = ((size_t)(n*S + 2*yo)*S + 2*xo)*C + c;
        size_t b10 = b00 + (size_t)S*C;
        float v00 = __bfloat162float(ihi[b00])   + __bfloat162float(ilo[b00]);
        float v01 = __bfloat162float(ihi[b00+C]) + __bfloat162float(ilo[b00+C]);
        float v10 = __bfloat162float(ihi[b10])   + __bfloat162float(ilo[b10]);
        float v11 = __bfloat162float(ihi[b10+C]) + __bfloat162float(ilo[b10+C]);
        float m = fmaxf(fmaxf(v00, v01), fmaxf(v10, v11));
        pout[((size_t)(n*C + c)*So + yo)*So + xo] = m;
        if (writeN) {
            size_t o = ((size_t)(n*So + yo)*So + xo)*C + c;
            bf16 hh = __float2bfloat16(m);
            ohi[o] = hh;
            olo[o] = __float2bfloat16(m - __bfloat162float(hh));
        }
    }
}

__global__ void perc_kernel(const float* __restrict__ p, int C, int S) {
    const size_t per = (size_t)C*S*S;
    const size_t total = 2*per;
    const size_t stride = (size_t)gridDim.x * blockDim.x;
    double s = 0.0;
    for (size_t i = blockIdx.x*(size_t)blockDim.x + threadIdx.x; i < total; i += stride) {
        float po = p[i], pg = p[i + 2*per], pc = p[i + 4*per];
        s += (double)(fabsf(po-pg) + fabsf(pc-pg));
    }
    s = blockReduceSum(s);
    if (threadIdx.x == 0) atomicAdd(&g_acc[2], s);
}

__global__ __launch_bounds__(256, 2)
void style_kernel(const float* __restrict__ p, int C, int S, int va, double scale) {
    const int tid = threadIdx.x;
    const int tx = tid & 15, ty = tid >> 4;
    const int bc = blockIdx.z;
    const int b = bc / C, c = bc - b*C;
    const int wt = blockIdx.y * 64, vt = blockIdx.x * 64;
    const float* A = p + ((size_t)((va*2+b)*C + c)) * S * S;
    const float* G = p + ((size_t)((2   +b)*C + c)) * S * S;

    __shared__ __align__(16) float s_aw[32][64], s_av[32][64];
    __shared__ __align__(16) float s_gw[32][64], s_gv[32][64];

    u64 accA[4][2], accG[4][2];
    #pragma unroll
    for (int i = 0; i < 4; i++) { accA[i][0]=0; accA[i][1]=0; accG[i][0]=0; accG[i][1]=0; }

    for (int k0 = 0; k0 < S; k0 += 32) {
        __syncthreads();
        for (int i = tid; i < 32*64; i += 256) {
            int kk = i >> 6, col = i & 63;
            size_t row = (size_t)(k0+kk)*S;
            s_aw[kk][col] = A[row + wt + col];
            s_av[kk][col] = A[row + vt + col];
            s_gw[kk][col] = G[row + wt + col];
            s_gv[kk][col] = G[row + vt + col];
        }
        __syncthreads();
        #pragma unroll 4
        for (int kk = 0; kk < 32; kk++) {
            float4 aw4 = *(const float4*)&s_aw[kk][ty*4];
            float4 gw4 = *(const float4*)&s_gw[kk][ty*4];
            ulonglong2 av = *(const ulonglong2*)&s_av[kk][tx*4];
            ulonglong2 gv = *(const ulonglong2*)&s_gv[kk][tx*4];
            u64 aw[4] = {pk(aw4.x,aw4.x), pk(aw4.y,aw4.y), pk(aw4.z,aw4.z), pk(aw4.w,aw4.w)};
            u64 gw[4] = {pk(gw4.x,gw4.x), pk(gw4.y,gw4.y), pk(gw4.z,gw4.z), pk(gw4.w,gw4.w)};
            #pragma unroll
            for (int i = 0; i < 4; i++) {
                accA[i][0] = fma2(aw[i], av.x, accA[i][0]);
                accA[i][1] = fma2(aw[i], av.y, accA[i][1]);
                accG[i][0] = fma2(gw[i], gv.x, accG[i][0]);
                accG[i][1] = fma2(gw[i], gv.y, accG[i][1]);
            }
        }
    }
    double s = 0.0;
    #pragma unroll
    for (int i = 0; i < 4; i++) {
        #pragma unroll
        for (int j = 0; j < 2; j++) {
            float2 a = upk(accA[i][j]), g = upk(accG[i][j]);
            s += (double)fabsf(a.x - g.x) + (double)fabsf(a.y - g.y);
        }
    }
    s = blockReduceSum(s);
    if (threadIdx.x == 0) atomicAdd(&g_acc[3], scale * s);
}

__global__ void finish_kernel(float* __restrict__ out) {
    const double N    = 3.0*512.0*512.0*2.0;
    const double Nigt = 2.0*64.0*256.0*256.0;
    out[0] = (float)(2.0*g_acc[0]/N + g_acc[1]/N + g_acc[2]/Nigt + g_acc[3]);
}

extern "C" void kernel_launch(void* const* d_in, const int* in_sizes, int n_in,
                              void* d_out, int out_size) {
    const float* igt  = (const float*)d_in[0];
    const float* iout = (const float*)d_in[1];
    const float* mask = (const float*)d_in[2];
    const float* w[7]; const float* bs[7];
    for (int i = 0; i < 7; i++) { w[i] = (const float*)d_in[3+2*i]; bs[i] = (const float*)d_in[4+2*i]; }

    float *x0, *bufA, *p1, *p2, *p3;
    bf16 *hA, *lA, *hB, *lB;
    cudaGetSymbolAddress((void**)&x0, g_x0);
    cudaGetSymbolAddress((void**)&bufA, g_bufA);
    cudaGetSymbolAddress((void**)&p1, g_p1);
    cudaGetSymbolAddress((void**)&p2, g_p2);
    cudaGetSymbolAddress((void**)&p3, g_p3);
    cudaGetSymbolAddress((void**)&hA, g_hA);
    cudaGetSymbolAddress((void**)&lA, g_lA);
    cudaGetSymbolAddress((void**)&hB, g_hB);
    cudaGetSymbolAddress((void**)&lB, g_lB);

    const int SM64  = 2*(2*128*144 + 2*64*144)  + 128;   // 110720
    const int SM128 = 2*(2*128*144 + 2*128*144) + 128;   // 147584
    cudaFuncSetAttribute(conv_mma<64>,  cudaFuncAttributeMaxDynamicSharedMemorySize, SM64);
    cudaFuncSetAttribute(conv_mma<128>, cudaFuncAttributeMaxDynamicSharedMemorySize, SM128);

    zero_acc<<<1, 32>>>();
    prep_kernel<<<2048, 256>>>(igt, iout, mask);

    prep_w<<<128, 256>>>(w[1],  64,  64,  64, 0);
    prep_w<<<128, 256>>>(w[2],  64, 128, 128, 36864);
    prep_w<<<128, 256>>>(w[3], 128, 128, 128, 110592);
    prep_w<<<256, 256>>>(w[4], 128, 256, 128, 258048);
    prep_w<<<256, 256>>>(w[5], 256, 256, 128, 552960);
    prep_w<<<256, 256>>>(w[6], 256, 256, 128, 1142784);

    conv_l0<<<dim3(8,32,48), 256>>>(x0, w[0], bs[0], bufA, 512);
    to_nhwc<<<dim3(8192,6), 256>>>(bufA, hA, lA);

    conv_mma<64> <<<dim3(4,512,6),  256, SM64 >>>(hA, lA, bs[1], hB, lB,  64,  64, 512, 0);
    pool_mma<<<4096, 256>>>(hB, lB, p1, hA, lA, 64, 512, 1);
    conv_mma<128><<<dim3(2,256,6),  256, SM128>>>(hA, lA, bs[2], hB, lB,  64, 128, 256, 36864);
    conv_mma<128><<<dim3(2,256,6),  256, SM128>>>(hB, lB, bs[3], hA, lA, 128, 128, 256, 110592);
    pool_mma<<<2048, 256>>>(hA, lA, p2, hB, lB, 128, 256, 1);
    conv_mma<128><<<dim3(1,128,12), 256, SM128>>>(hB, lB, bs[4], hA, lA, 128, 256, 128, 258048);
    conv_mma<128><<<dim3(1,128,12), 256, SM128>>>(hA, lA, bs[5], hB, lB, 256, 256, 128, 552960);
    conv_mma<128><<<dim3(1,128,12), 256, SM128>>>(hB, lB, bs[6], hA, lA, 256, 256, 128, 1142784);
    pool_mma<<<1024, 256>>>(hA, lA, p3, hB, lB, 256, 128, 0);

    perc_kernel<<<2048, 256>>>(p1,  64, 256);
    perc_kernel<<<2048, 256>>>(p2, 128, 128);
    perc_kernel<<<1024, 256>>>(p3, 256,  64);

    const double s1 = 1.0/((double)64 *256*256)/( 64.0* 64.0);
    const double s2 = 1.0/((double)128*128*128)/(128.0*128.0);
    const double s3 = 1.0/((double)256* 64* 64)/(256.0*256.0);
    style_kernel<<<dim3(4,4,128), 256>>>(p1,  64, 256, 2, s1);
    style_kernel<<<dim3(4,4,128), 256>>>(p1,  64, 256, 0, s1);
    style_kernel<<<dim3(2,2,256), 256>>>(p2, 128, 128, 2, s2);
    style_kernel<<<dim3(2,2,256), 256>>>(p2, 128, 128, 0, s2);
    style_kernel<<<dim3(1,1,512), 256>>>(p3, 256,  64, 2, s3);
    style_kernel<<<dim3(1,1,512), 256>>>(p3, 256,  64, 0, s3);

    finish_kernel<<<1, 1>>>((float*)d_out);
}

// round 14
// speedup vs baseline: 6.1192x; 1.3447x over previous
#include <cuda_runtime.h>
#include <cuda_bf16.h>
#include <math.h>
#include <stdint.h>

#define HW0 (512*512)
typedef unsigned long long u64;
typedef __nv_bfloat16 bf16;

__device__ float g_x0  [6*3*HW0];
__device__ float g_p1  [6*64*256*256];
__device__ float g_p2  [6*128*128*128];
__device__ float g_p3  [6*256*64*64];
__device__ double g_acc[4];
__device__ bf16 g_hA[100663296];
__device__ bf16 g_lA[100663296];
__device__ bf16 g_hB[100663296];
__device__ bf16 g_lB[100663296];
__device__ bf16 g_wHi[1732608];

__device__ __forceinline__ u64 pk(float lo, float hi) {
    u64 r; asm("mov.b64 %0,{%1,%2};" : "=l"(r) : "f"(lo), "f"(hi)); return r;
}
__device__ __forceinline__ float2 upk(u64 v) {
    float2 r; asm("mov.b64 {%0,%1},%2;" : "=f"(r.x), "=f"(r.y) : "l"(v)); return r;
}
__device__ __forceinline__ u64 fma2(u64 a, u64 b, u64 c) {
    u64 d; asm("fma.rn.f32x2 %0,%1,%2,%3;" : "=l"(d) : "l"(a), "l"(b), "l"(c)); return d;
}
__device__ __forceinline__ void cp4(uint32_t s, const float* g, bool ok) {
    asm volatile("cp.async.ca.shared.global [%0],[%1],4,%2;" :: "r"(s), "l"(g), "r"(ok?4:0));
}
__device__ __forceinline__ void cp16(uint32_t s, const void* g, bool ok) {
    asm volatile("cp.async.cg.shared.global [%0],[%1],16,%2;" :: "r"(s), "l"(g), "r"(ok?16:0));
}
__device__ __forceinline__ void cp_commit() { asm volatile("cp.async.commit_group;"); }
template<int N> __device__ __forceinline__ void cp_wait() {
    asm volatile("cp.async.wait_group %0;" :: "n"(N));
}
__device__ __forceinline__ void ldsm4(uint32_t* r, uint32_t a) {
    asm volatile("ldmatrix.sync.aligned.m8n8.x4.shared.b16 {%0,%1,%2,%3},[%4];"
        : "=r"(r[0]), "=r"(r[1]), "=r"(r[2]), "=r"(r[3]) : "r"(a));
}
__device__ __forceinline__ void mma16816(float* c, const uint32_t* a, const uint32_t* b) {
    asm volatile("mma.sync.aligned.m16n8k16.row.col.f32.bf16.bf16.f32 "
        "{%0,%1,%2,%3},{%4,%5,%6,%7},{%8,%9},{%0,%1,%2,%3};"
        : "+f"(c[0]), "+f"(c[1]), "+f"(c[2]), "+f"(c[3])
        : "r"(a[0]), "r"(a[1]), "r"(a[2]), "r"(a[3]), "r"(b[0]), "r"(b[1]));
}

__device__ __forceinline__ double blockReduceSum(double v) {
    __shared__ double s[32];
    int lane = threadIdx.x & 31, wid = threadIdx.x >> 5;
    #pragma unroll
    for (int o = 16; o; o >>= 1) v += __shfl_down_sync(0xffffffffu, v, o);
    if (lane == 0) s[wid] = v;
    __syncthreads();
    int nw = blockDim.x >> 5;
    v = (threadIdx.x < nw) ? s[threadIdx.x] : 0.0;
    if (wid == 0) {
        #pragma unroll
        for (int o = 16; o; o >>= 1) v += __shfl_down_sync(0xffffffffu, v, o);
    }
    return v;
}

__global__ void zero_acc() { if (threadIdx.x < 4) g_acc[threadIdx.x] = 0.0; }

__global__ void prep_kernel(const float* __restrict__ igt, const float* __restrict__ iout,
                            const float* __restrict__ mask) {
    double hole = 0.0, valid = 0.0;
    const int total = 2*3*HW0;
    int stride = gridDim.x * blockDim.x;
    for (int i = blockIdx.x*blockDim.x + threadIdx.x; i < total; i += stride) {
        int hw = i % HW0, t = i / HW0, b = t / 3;
        float g = igt[i], o = iout[i];
        float mv = mask[b*HW0 + hw];
        float ad = fabsf(o - g);
        bool m = (mv != 0.0f);
        if (m) valid += (double)ad; else hole += (double)ad;
        g_x0[i] = o; g_x0[i + 6*HW0] = g; g_x0[i + 12*HW0] = m ? g : o;
    }
    hole = blockReduceSum(hole);
    __syncthreads();
    valid = blockReduceSum(valid);
    if (threadIdx.x == 0) { atomicAdd(&g_acc[0], hole); atomicAdd(&g_acc[1], valid); }
}

// Weight prepack: fp32 OIHW -> hi bf16 blocks [k9][cog][chunk]: N rows x 64 ci
__global__ void prep_w(const float* __restrict__ w, int CIN, int COUT, int N, int base) {
    int ncog = COUT / N, chunks = CIN >> 6;
    int total = 9*COUT*CIN;
    int stride = gridDim.x*blockDim.x;
    for (int i = blockIdx.x*blockDim.x + threadIdx.x; i < total; i += stride) {
        int inner = i % (N*64), blk = i / (N*64);
        int chunk = blk % chunks; int r1 = blk / chunks;
        int cog = r1 % ncog; int k9 = r1 / ncog;
        int row = inner >> 6, ci = inner & 63;
        int co = cog*N + row, c = chunk*64 + ci;
        int dy = k9/3, dx = k9 - dy*3;
        float v = w[((size_t)(co*CIN + c)*3 + dy)*3 + dx];
        g_wHi[(size_t)base + (size_t)blk*(N*64) + inner] = __float2bfloat16(v);
    }
}

// L0 direct FFMA2 conv (CIN=3), writes NHWC hi/lo bf16 directly
__global__ __launch_bounds__(256, 3)
void conv_l0(const float* __restrict__ in, const float* __restrict__ wgt,
             const float* __restrict__ bias, bf16* __restrict__ ohi,
             bf16* __restrict__ olo, int S)
{
    const int CIN = 3, COUT = 64;
    __shared__ __align__(16) float s_in[4][18*68];
    __shared__ __align__(16) u64 s_w2[4][3][4][4];
    const int tid = threadIdx.x;
    const int tx = tid & 15, ty = tid >> 4;
    const int n = blockIdx.z >> 3, cog = blockIdx.z & 7;
    const int w0 = blockIdx.x*64, h0 = blockIdx.y*16;
    const float* inb = in + (size_t)n*CIN*S*S;
    const float* wb = wgt + (size_t)(cog*8)*CIN*9;

    u64 acc[4][4];
    #pragma unroll
    for (int cp = 0; cp < 4; cp++) { acc[cp][0]=0; acc[cp][1]=0; acc[cp][2]=0; acc[cp][3]=0; }

    uint32_t sb = (uint32_t)__cvta_generic_to_shared(&s_in[0][0]);
    for (int i = tid; i < 3*1188; i += 256) {
        int ci = i/1188, rem = i - ci*1188;
        int r = rem/66, c = rem - r*66;
        int h = h0 + r - 1, w = w0 + c - 1;
        bool ok = ((unsigned)h < (unsigned)S) & ((unsigned)w < (unsigned)S);
        const float* g = ok ? inb + ((size_t)ci*S + h)*S + w : inb;
        cp4(sb + (uint32_t)((ci*18 + r)*68 + c)*4u, g, ok);
    }
    cp_commit();
    if (tid < 108) {
        int cp = tid/27, rem = tid - cp*27, ci = rem/9, k = rem - ci*9;
        int dy = k/3, dx = k - dy*3;
        float lo = __ldg(wb + (size_t)(2*cp)*27 + (size_t)ci*9 + k);
        float hi = __ldg(wb + (size_t)(2*cp+1)*27 + (size_t)ci*9 + k);
        s_w2[ci][dy][cp][dx] = pk(lo, hi);
    }
    cp_wait<0>();
    __syncthreads();

    #pragma unroll
    for (int ci = 0; ci < 3; ci++) {
        #pragma unroll
        for (int dy = 0; dy < 3; dy++) {
            const float* row = &s_in[ci][(ty+dy)*68 + tx*4];
            float4 q = *(const float4*)row;
            float v4 = row[4], v5 = row[5];
            u64 d0=pk(q.x,q.x), d1=pk(q.y,q.y), d2=pk(q.z,q.z), d3=pk(q.w,q.w), d4=pk(v4,v4), d5=pk(v5,v5);
            #pragma unroll
            for (int cp = 0; cp < 4; cp++) {
                const u64* wr = s_w2[ci][dy][cp];
                ulonglong2 w01 = *(const ulonglong2*)wr;
                u64 w2v = wr[2];
                acc[cp][0]=fma2(d0,w01.x,acc[cp][0]); acc[cp][1]=fma2(d1,w01.x,acc[cp][1]);
                acc[cp][2]=fma2(d2,w01.x,acc[cp][2]); acc[cp][3]=fma2(d3,w01.x,acc[cp][3]);
                acc[cp][0]=fma2(d1,w01.y,acc[cp][0]); acc[cp][1]=fma2(d2,w01.y,acc[cp][1]);
                acc[cp][2]=fma2(d3,w01.y,acc[cp][2]); acc[cp][3]=fma2(d4,w01.y,acc[cp][3]);
                acc[cp][0]=fma2(d2,w2v,acc[cp][0]);  acc[cp][1]=fma2(d3,w2v,acc[cp][1]);
                acc[cp][2]=fma2(d4,w2v,acc[cp][2]);  acc[cp][3]=fma2(d5,w2v,acc[cp][3]);
            }
        }
    }
    const int h = h0 + ty, w = w0 + tx*4;
    float bv[8];
    #pragma unroll
    for (int c = 0; c < 8; c++) bv[c] = bias[cog*8 + c];
    #pragma unroll
    for (int p = 0; p < 4; p++) {
        __align__(16) bf16 hi8[8];
        __align__(16) bf16 lo8[8];
        #pragma unroll
        for (int cp = 0; cp < 4; cp++) {
            float2 a = upk(acc[cp][p]);
            float v0 = fmaxf(a.x + bv[2*cp],   0.f);
            float v1 = fmaxf(a.y + bv[2*cp+1], 0.f);
            hi8[2*cp]   = __float2bfloat16(v0);
            lo8[2*cp]   = __float2bfloat16(v0 - __bfloat162float(hi8[2*cp]));
            hi8[2*cp+1] = __float2bfloat16(v1);
            lo8[2*cp+1] = __float2bfloat16(v1 - __bfloat162float(hi8[2*cp+1]));
        }
        size_t o = ((size_t)(n*S + h)*S + (w+p))*64 + cog*8;
        *(uint4*)(ohi + o) = *(uint4*)hi8;
        *(uint4*)(olo + o) = *(uint4*)lo8;
    }
}

// ---------------------------------------------------------------------------
// mma.sync implicit-GEMM conv. M=128 pixels, N=NT couts, K=64-ci chunks x 9
// shifts. Exact-fp32 activations x bf16 weights: D += Ahi*Bhi + Alo*Bhi.
// SMEM rows padded to 144B (conflict-free ldmatrix). cp.async double buffer.
// ---------------------------------------------------------------------------
template<int NT>
__global__ __launch_bounds__(256, 1)
void conv_mma(const bf16* __restrict__ ihi, const bf16* __restrict__ ilo,
              const float* __restrict__ bias, bf16* __restrict__ ohi, bf16* __restrict__ olo,
              int CIN, int COUT, int S, int wbase)
{
    constexpr int WARPS_M = (NT == 128) ? 2 : 4;
    constexpr int MT = (NT == 128) ? 4 : 2;
    constexpr int MW = MT*16;
    constexpr uint32_t ASZ = 128*144u;
    constexpr uint32_t BSZ = (uint32_t)NT*144u;
    constexpr uint32_t BUFSZ = 2*ASZ + BSZ;

    extern __shared__ __align__(16) char dsm[];
    const int tid = threadIdx.x;
    const int wid = tid >> 5, lane = tid & 31;
    const int wm = wid % WARPS_M, wn = wid / WARPS_M;
    const int ncog = COUT / NT;
    const int chunks = CIN >> 6;
    const int n = blockIdx.z / ncog, cog = blockIdx.z - n*ncog;
    const int w0 = blockIdx.x << 7;
    const int h = blockIdx.y;

    uint32_t sbase = ((uint32_t)__cvta_generic_to_shared(dsm) + 127u) & ~127u;
    const int NS = 9*chunks;

    float acc[MT][4][4];
    #pragma unroll
    for (int mt = 0; mt < MT; mt++)
        #pragma unroll
        for (int nt = 0; nt < 4; nt++)
            { acc[mt][nt][0]=0.f; acc[mt][nt][1]=0.f; acc[mt][nt][2]=0.f; acc[mt][nt][3]=0.f; }

    const uint32_t rA = (uint32_t)(lane & 15)*144u + (uint32_t)(lane >> 4)*16u;
    const uint32_t rB = (uint32_t)((lane & 7) + ((lane >> 4) << 3))*144u
                      + (uint32_t)((lane >> 3) & 1)*16u;

    auto build = [&](int st, int fb) {
        uint32_t bo = sbase + (uint32_t)fb*BUFSZ;
        int shift = st / chunks, chunk = st - shift*chunks;
        int dy = shift/3, dx = shift - dy*3;
        int hh = h + dy - 1;
        bool hok = ((unsigned)hh < (unsigned)S);
        int hcl = hok ? hh : 0;
        for (int i = tid; i < 2048; i += 256) {
            int term = i >> 10, r = (i >> 3) & 127, seg = i & 7;
            int wp = w0 + r + dx - 1;
            bool ok = hok && ((unsigned)wp < (unsigned)S);
            int wcl = ok ? wp : 0;
            const bf16* src = term ? ilo : ihi;
            const void* g = src + ((size_t)(n*S + hcl)*S + wcl)*CIN + chunk*64 + seg*8;
            cp16(bo + (uint32_t)term*ASZ + (uint32_t)r*144u + (uint32_t)seg*16u, g, ok);
        }
        size_t wblk = (size_t)wbase + (size_t)((shift*ncog + cog)*chunks + chunk)*((size_t)NT*64);
        constexpr int bq = NT*8;
        for (int i = tid; i < bq; i += 256) {
            cp16(bo + 2*ASZ + (uint32_t)(i >> 3)*144u + (uint32_t)(i & 7)*16u,
                 g_wHi + wblk + (size_t)i*8, true);
        }
        cp_commit();
    };

    auto compute = [&](int fb) {
        uint32_t bo = sbase + (uint32_t)fb*BUFSZ;
        uint32_t Ah = bo, Al = bo + ASZ, Bb = bo + 2*ASZ;
        #pragma unroll
        for (int k16 = 0; k16 < 4; k16++) {
            uint32_t bf[2][4];
            #pragma unroll
            for (int p = 0; p < 2; p++)
                ldsm4(bf[p], Bb + (uint32_t)(wn*32 + p*16)*144u + rB + (uint32_t)k16*32u);
            uint32_t ah[MT][4];
            #pragma unroll
            for (int mt = 0; mt < MT; mt++)
                ldsm4(ah[mt], Ah + (uint32_t)(wm*MW + mt*16)*144u + rA + (uint32_t)k16*32u);
            #pragma unroll
            for (int mt = 0; mt < MT; mt++)
                #pragma unroll
                for (int nt = 0; nt < 4; nt++)
                    mma16816(acc[mt][nt], ah[mt], &bf[nt >> 1][(nt & 1)*2]);
            #pragma unroll
            for (int mt = 0; mt < MT; mt++)
                ldsm4(ah[mt], Al + (uint32_t)(wm*MW + mt*16)*144u + rA + (uint32_t)k16*32u);
            #pragma unroll
            for (int mt = 0; mt < MT; mt++)
                #pragma unroll
                for (int nt = 0; nt < 4; nt++)
                    mma16816(acc[mt][nt], ah[mt], &bf[nt >> 1][(nt & 1)*2]);
        }
    };

    build(0, 0);
    for (int st = 0; st < NS; st++) {
        int fb = st & 1;
        if (st + 1 < NS) { build(st + 1, fb ^ 1); cp_wait<1>(); }
        else             { cp_wait<0>(); }
        __syncthreads();
        compute(fb);
        __syncthreads();
    }

    // Epilogue: bias + ReLU, NHWC hi/lo
    float b2[4][2];
    #pragma unroll
    for (int nt = 0; nt < 4; nt++) {
        int co = nt*8 + (lane & 3)*2;
        b2[nt][0] = bias[cog*NT + wn*32 + co];
        b2[nt][1] = bias[cog*NT + wn*32 + co + 1];
    }
    #pragma unroll
    for (int mt = 0; mt < MT; mt++) {
        int r0 = wm*MW + mt*16 + (lane >> 2);
        #pragma unroll
        for (int half = 0; half < 2; half++) {
            int px = w0 + r0 + half*8;
            size_t ob = ((size_t)(n*S + h)*S + px)*COUT + (size_t)(cog*NT + wn*32);
            #pragma unroll
            for (int nt = 0; nt < 4; nt++) {
                int co = nt*8 + (lane & 3)*2;
                float v0 = fmaxf(acc[mt][nt][half*2]   + b2[nt][0], 0.f);
                float v1 = fmaxf(acc[mt][nt][half*2+1] + b2[nt][1], 0.f);
                bf16 h0 = __float2bfloat16(v0);
                bf16 h1 = __float2bfloat16(v1);
                __nv_bfloat162 hp, lp;
                hp.x = h0; hp.y = h1;
                lp.x = __float2bfloat16(v0 - __bfloat162float(h0));
                lp.y = __float2bfloat16(v1 - __bfloat162float(h1));
                *(__nv_bfloat162*)(ohi + ob + co) = hp;
                *(__nv_bfloat162*)(olo + ob + co) = lp;
            }
        }
    }
}

// Pool: NHWC hi/lo -> NCHW fp32 + optional NHWC hi/lo
__global__ void pool_mma(const bf16* __restrict__ ihi, const bf16* __restrict__ ilo,
                         float* __restrict__ pout, bf16* __restrict__ ohi, bf16* __restrict__ olo,
                         int C, int S, int writeN)
{
    const int So = S >> 1;
    const size_t total = (size_t)6*So*So*C;
    const size_t stride = (size_t)gridDim.x*blockDim.x;
    for (size_t i = blockIdx.x*(size_t)blockDim.x + threadIdx.x; i < total; i += stride) {
        int c = (int)(i % C);
        size_t t = i / C;
        int xo = (int)(t % So); t /= So;
        int yo = (int)(t % So);
        int n = (int)(t / So);
        size_t b00 = ((size_t)(n*S + 2*yo)*S + 2*xo)*C + c;
        size_t b10 = b00 + (size_t)S*C;
        float v00 = __bfloat162float(ihi[b00])   + __bfloat162float(ilo[b00]);
        float v01 = __bfloat162float(ihi[b00+C]) + __bfloat162float(ilo[b00+C]);
        float v10 = __bfloat162float(ihi[b10])   + __bfloat162float(ilo[b10]);
        float v11 = __bfloat162float(ihi[b10+C]) + __bfloat162float(ilo[b10+C]);
        float m = fmaxf(fmaxf(v00, v01), fmaxf(v10, v11));
        pout[((size_t)(n*C + c)*So + yo)*So + xo] = m;
        if (writeN) {
            size_t o = ((size_t)(n*So + yo)*So + xo)*C + c;
            bf16 hh = __float2bfloat16(m);
            ohi[o] = hh;
            olo[o] = __float2bfloat16(m - __bfloat162float(hh));
        }
    }
}

__global__ void perc_kernel(const float* __restrict__ p, int C, int S) {
    const size_t per = (size_t)C*S*S;
    const size_t total = 2*per;
    const size_t stride = (size_t)gridDim.x * blockDim.x;
    double s = 0.0;
    for (size_t i = blockIdx.x*(size_t)blockDim.x + threadIdx.x; i < total; i += stride) {
        float po = p[i], pg = p[i + 2*per], pc = p[i + 4*per];
        s += (double)(fabsf(po-pg) + fabsf(pc-pg));
    }
    s = blockReduceSum(s);
    if (threadIdx.x == 0) atomicAdd(&g_acc[2], s);
}

__global__ __launch_bounds__(256, 2)
void style_kernel(const float* __restrict__ p, int C, int S, int va, double scale) {
    const int tid = threadIdx.x;
    const int tx = tid & 15, ty = tid >> 4;
    const int bc = blockIdx.z;
    const int b = bc / C, c = bc - b*C;
    const int wt = blockIdx.y * 64, vt = blockIdx.x * 64;
    const float* A = p + ((size_t)((va*2+b)*C + c)) * S * S;
    const float* G = p + ((size_t)((2   +b)*C + c)) * S * S;

    __shared__ __align__(16) float s_aw[32][64], s_av[32][64];
    __shared__ __align__(16) float s_gw[32][64], s_gv[32][64];

    u64 accA[4][2], accG[4][2];
    #pragma unroll
    for (int i = 0; i < 4; i++) { accA[i][0]=0; accA[i][1]=0; accG[i][0]=0; accG[i][1]=0; }

    for (int k0 = 0; k0 < S; k0 += 32) {
        __syncthreads();
        for (int i = tid; i < 32*64; i += 256) {
            int kk = i >> 6, col = i & 63;
            size_t row = (size_t)(k0+kk)*S;
            s_aw[kk][col] = A[row + wt + col];
            s_av[kk][col] = A[row + vt + col];
            s_gw[kk][col] = G[row + wt + col];
            s_gv[kk][col] = G[row + vt + col];
        }
        __syncthreads();
        #pragma unroll 4
        for (int kk = 0; kk < 32; kk++) {
            float4 aw4 = *(const float4*)&s_aw[kk][ty*4];
            float4 gw4 = *(const float4*)&s_gw[kk][ty*4];
            ulonglong2 av = *(const ulonglong2*)&s_av[kk][tx*4];
            ulonglong2 gv = *(const ulonglong2*)&s_gv[kk][tx*4];
            u64 aw[4] = {pk(aw4.x,aw4.x), pk(aw4.y,aw4.y), pk(aw4.z,aw4.z), pk(aw4.w,aw4.w)};
            u64 gw[4] = {pk(gw4.x,gw4.x), pk(gw4.y,gw4.y), pk(gw4.z,gw4.z), pk(gw4.w,gw4.w)};
            #pragma unroll
            for (int i = 0; i < 4; i++) {
                accA[i][0] = fma2(aw[i], av.x, accA[i][0]);
                accA[i][1] = fma2(aw[i], av.y, accA[i][1]);
                accG[i][0] = fma2(gw[i], gv.x, accG[i][0]);
                accG[i][1] = fma2(gw[i], gv.y, accG[i][1]);
            }
        }
    }
    double s = 0.0;
    #pragma unroll
    for (int i = 0; i < 4; i++) {
        #pragma unroll
        for (int j = 0; j < 2; j++) {
            float2 a = upk(accA[i][j]), g = upk(accG[i][j]);
            s += (double)fabsf(a.x - g.x) + (double)fabsf(a.y - g.y);
        }
    }
    s = blockReduceSum(s);
    if (threadIdx.x == 0) atomicAdd(&g_acc[3], scale * s);
}

__global__ void finish_kernel(float* __restrict__ out) {
    const double N    = 3.0*512.0*512.0*2.0;
    const double Nigt = 2.0*64.0*256.0*256.0;
    out[0] = (float)(2.0*g_acc[0]/N + g_acc[1]/N + g_acc[2]/Nigt + g_acc[3]);
}

extern "C" void kernel_launch(void* const* d_in, const int* in_sizes, int n_in,
                              void* d_out, int out_size) {
    const float* igt  = (const float*)d_in[0];
    const float* iout = (const float*)d_in[1];
    const float* mask = (const float*)d_in[2];
    const float* w[7]; const float* bs[7];
    for (int i = 0; i < 7; i++) { w[i] = (const float*)d_in[3+2*i]; bs[i] = (const float*)d_in[4+2*i]; }

    float *x0, *p1, *p2, *p3;
    bf16 *hA, *lA, *hB, *lB;
    cudaGetSymbolAddress((void**)&x0, g_x0);
    cudaGetSymbolAddress((void**)&p1, g_p1);
    cudaGetSymbolAddress((void**)&p2, g_p2);
    cudaGetSymbolAddress((void**)&p3, g_p3);
    cudaGetSymbolAddress((void**)&hA, g_hA);
    cudaGetSymbolAddress((void**)&lA, g_lA);
    cudaGetSymbolAddress((void**)&hB, g_hB);
    cudaGetSymbolAddress((void**)&lB, g_lB);

    const int SM64  = 2*(2*128*144 + 64*144)  + 128;   // 92288
    const int SM128 = 2*(2*128*144 + 128*144) + 128;   // 110720
    cudaFuncSetAttribute(conv_mma<64>,  cudaFuncAttributeMaxDynamicSharedMemorySize, SM64);
    cudaFuncSetAttribute(conv_mma<128>, cudaFuncAttributeMaxDynamicSharedMemorySize, SM128);

    zero_acc<<<1, 32>>>();
    prep_kernel<<<2048, 256>>>(igt, iout, mask);

    prep_w<<<128, 256>>>(w[1],  64,  64,  64, 0);
    prep_w<<<128, 256>>>(w[2],  64, 128, 128, 36864);
    prep_w<<<128, 256>>>(w[3], 128, 128, 128, 110592);
    prep_w<<<256, 256>>>(w[4], 128, 256, 128, 258048);
    prep_w<<<256, 256>>>(w[5], 256, 256, 128, 552960);
    prep_w<<<256, 256>>>(w[6], 256, 256, 128, 1142784);

    conv_l0<<<dim3(8,32,48), 256>>>(x0, w[0], bs[0], hA, lA, 512);

    conv_mma<64> <<<dim3(4,512,6),  256, SM64 >>>(hA, lA, bs[1], hB, lB,  64,  64, 512, 0);
    pool_mma<<<4096, 256>>>(hB, lB, p1, hA, lA, 64, 512, 1);
    conv_mma<128><<<dim3(2,256,6),  256, SM128>>>(hA, lA, bs[2], hB, lB,  64, 128, 256, 36864);
    conv_mma<128><<<dim3(2,256,6),  256, SM128>>>(hB, lB, bs[3], hA, lA, 128, 128, 256, 110592);
    pool_mma<<<2048, 256>>>(hA, lA, p2, hB, lB, 128, 256, 1);
    conv_mma<128><<<dim3(1,128,12), 256, SM128>>>(hB, lB, bs[4], hA, lA, 128, 256, 128, 258048);
    conv_mma<128><<<dim3(1,128,12), 256, SM128>>>(hA, lA, bs[5], hB, lB, 256, 256, 128, 552960);
    conv_mma<128><<<dim3(1,128,12), 256, SM128>>>(hB, lB, bs[6], hA, lA, 256, 256, 128, 1142784);
    pool_mma<<<1024, 256>>>(hA, lA, p3, hB, lB, 256, 128, 0);

    perc_kernel<<<2048, 256>>>(p1,  64, 256);
    perc_kernel<<<2048, 256>>>(p2, 128, 128);
    perc_kernel<<<1024, 256>>>(p3, 256,  64);

    const double s1 = 1.0/((double)64 *256*256)/( 64.0* 64.0);
    const double s2 = 1.0/((double)128*128*128)/(128.0*128.0);
    const double s3 = 1.0/((double)256* 64* 64)/(256.0*256.0);
    style_kernel<<<dim3(4,4,128), 256>>>(p1,  64, 256, 2, s1);
    style_kernel<<<dim3(4,4,128), 256>>>(p1,  64, 256, 0, s1);
    style_kernel<<<dim3(2,2,256), 256>>>(p2, 128, 128, 2, s2);
    style_kernel<<<dim3(2,2,256), 256>>>(p2, 128, 128, 0, s2);
    style_kernel<<<dim3(1,1,512), 256>>>(p3, 256,  64, 2, s3);
    style_kernel<<<dim3(1,1,512), 256>>>(p3, 256,  64, 0, s3);

    finish_kernel<<<1, 1>>>((float*)d_out);
}

// round 15
// speedup vs baseline: 7.1304x; 1.1653x over previous
#include <cuda_runtime.h>
#include <cuda_bf16.h>
#include <math.h>
#include <stdint.h>

#define HW0 (512*512)
typedef unsigned long long u64;
typedef __nv_bfloat16 bf16;

__device__ float g_x0  [6*3*HW0];
__device__ float g_p1  [6*64*256*256];
__device__ float g_p2  [6*128*128*128];
__device__ float g_p3  [6*256*64*64];
__device__ double g_acc[4];
__device__ bf16 g_hA[100663296];
__device__ bf16 g_lA[100663296];
__device__ bf16 g_hB[100663296];
__device__ bf16 g_lB[100663296];
__device__ bf16 g_wHi[1732608];

__device__ __forceinline__ u64 pk(float lo, float hi) {
    u64 r; asm("mov.b64 %0,{%1,%2};" : "=l"(r) : "f"(lo), "f"(hi)); return r;
}
__device__ __forceinline__ float2 upk(u64 v) {
    float2 r; asm("mov.b64 {%0,%1},%2;" : "=f"(r.x), "=f"(r.y) : "l"(v)); return r;
}
__device__ __forceinline__ u64 fma2(u64 a, u64 b, u64 c) {
    u64 d; asm("fma.rn.f32x2 %0,%1,%2,%3;" : "=l"(d) : "l"(a), "l"(b), "l"(c)); return d;
}
__device__ __forceinline__ void cp4(uint32_t s, const float* g, bool ok) {
    asm volatile("cp.async.ca.shared.global [%0],[%1],4,%2;" :: "r"(s), "l"(g), "r"(ok?4:0));
}
__device__ __forceinline__ void cp16(uint32_t s, const void* g, bool ok) {
    asm volatile("cp.async.cg.shared.global [%0],[%1],16,%2;" :: "r"(s), "l"(g), "r"(ok?16:0));
}
__device__ __forceinline__ void cp_commit() { asm volatile("cp.async.commit_group;"); }
template<int N> __device__ __forceinline__ void cp_wait() {
    asm volatile("cp.async.wait_group %0;" :: "n"(N));
}
__device__ __forceinline__ void ldsm4(uint32_t* r, uint32_t a) {
    asm volatile("ldmatrix.sync.aligned.m8n8.x4.shared.b16 {%0,%1,%2,%3},[%4];"
        : "=r"(r[0]), "=r"(r[1]), "=r"(r[2]), "=r"(r[3]) : "r"(a));
}
__device__ __forceinline__ void mma16816(float* c, const uint32_t* a, const uint32_t* b) {
    asm volatile("mma.sync.aligned.m16n8k16.row.col.f32.bf16.bf16.f32 "
        "{%0,%1,%2,%3},{%4,%5,%6,%7},{%8,%9},{%0,%1,%2,%3};"
        : "+f"(c[0]), "+f"(c[1]), "+f"(c[2]), "+f"(c[3])
        : "r"(a[0]), "r"(a[1]), "r"(a[2]), "r"(a[3]), "r"(b[0]), "r"(b[1]));
}

__device__ __forceinline__ double blockReduceSum(double v) {
    __shared__ double s[32];
    int lane = threadIdx.x & 31, wid = threadIdx.x >> 5;
    #pragma unroll
    for (int o = 16; o; o >>= 1) v += __shfl_down_sync(0xffffffffu, v, o);
    if (lane == 0) s[wid] = v;
    __syncthreads();
    int nw = blockDim.x >> 5;
    v = (threadIdx.x < nw) ? s[threadIdx.x] : 0.0;
    if (wid == 0) {
        #pragma unroll
        for (int o = 16; o; o >>= 1) v += __shfl_down_sync(0xffffffffu, v, o);
    }
    return v;
}

__global__ void zero_acc() { if (threadIdx.x < 4) g_acc[threadIdx.x] = 0.0; }

__global__ void prep_kernel(const float* __restrict__ igt, const float* __restrict__ iout,
                            const float* __restrict__ mask) {
    double hole = 0.0, valid = 0.0;
    const int total = 2*3*HW0;
    int stride = gridDim.x * blockDim.x;
    for (int i = blockIdx.x*blockDim.x + threadIdx.x; i < total; i += stride) {
        int hw = i % HW0, t = i / HW0, b = t / 3;
        float g = igt[i], o = iout[i];
        float mv = mask[b*HW0 + hw];
        float ad = fabsf(o - g);
        bool m = (mv != 0.0f);
        if (m) valid += (double)ad; else hole += (double)ad;
        g_x0[i] = o; g_x0[i + 6*HW0] = g; g_x0[i + 12*HW0] = m ? g : o;
    }
    hole = blockReduceSum(hole);
    __syncthreads();
    valid = blockReduceSum(valid);
    if (threadIdx.x == 0) { atomicAdd(&g_acc[0], hole); atomicAdd(&g_acc[1], valid); }
}

// Weight prepack: fp32 OIHW -> hi bf16 blocks [k9][cog][chunk]: N rows x 64 ci
__global__ void prep_w(const float* __restrict__ w, int CIN, int COUT, int N, int base) {
    int ncog = COUT / N, chunks = CIN >> 6;
    int total = 9*COUT*CIN;
    int stride = gridDim.x*blockDim.x;
    for (int i = blockIdx.x*blockDim.x + threadIdx.x; i < total; i += stride) {
        int inner = i % (N*64), blk = i / (N*64);
        int chunk = blk % chunks; int r1 = blk / chunks;
        int cog = r1 % ncog; int k9 = r1 / ncog;
        int row = inner >> 6, ci = inner & 63;
        int co = cog*N + row, c = chunk*64 + ci;
        int dy = k9/3, dx = k9 - dy*3;
        float v = w[((size_t)(co*CIN + c)*3 + dy)*3 + dx];
        g_wHi[(size_t)base + (size_t)blk*(N*64) + inner] = __float2bfloat16(v);
    }
}

// L0 direct FFMA2 conv (CIN=3), writes NHWC hi/lo bf16 directly
__global__ __launch_bounds__(256, 3)
void conv_l0(const float* __restrict__ in, const float* __restrict__ wgt,
             const float* __restrict__ bias, bf16* __restrict__ ohi,
             bf16* __restrict__ olo, int S)
{
    const int CIN = 3, COUT = 64;
    __shared__ __align__(16) float s_in[4][18*68];
    __shared__ __align__(16) u64 s_w2[4][3][4][4];
    const int tid = threadIdx.x;
    const int tx = tid & 15, ty = tid >> 4;
    const int n = blockIdx.z >> 3, cog = blockIdx.z & 7;
    const int w0 = blockIdx.x*64, h0 = blockIdx.y*16;
    const float* inb = in + (size_t)n*CIN*S*S;
    const float* wb = wgt + (size_t)(cog*8)*CIN*9;

    u64 acc[4][4];
    #pragma unroll
    for (int cp = 0; cp < 4; cp++) { acc[cp][0]=0; acc[cp][1]=0; acc[cp][2]=0; acc[cp][3]=0; }

    uint32_t sb = (uint32_t)__cvta_generic_to_shared(&s_in[0][0]);
    for (int i = tid; i < 3*1188; i += 256) {
        int ci = i/1188, rem = i - ci*1188;
        int r = rem/66, c = rem - r*66;
        int h = h0 + r - 1, w = w0 + c - 1;
        bool ok = ((unsigned)h < (unsigned)S) & ((unsigned)w < (unsigned)S);
        const float* g = ok ? inb + ((size_t)ci*S + h)*S + w : inb;
        cp4(sb + (uint32_t)((ci*18 + r)*68 + c)*4u, g, ok);
    }
    cp_commit();
    if (tid < 108) {
        int cp = tid/27, rem = tid - cp*27, ci = rem/9, k = rem - ci*9;
        int dy = k/3, dx = k - dy*3;
        float lo = __ldg(wb + (size_t)(2*cp)*27 + (size_t)ci*9 + k);
        float hi = __ldg(wb + (size_t)(2*cp+1)*27 + (size_t)ci*9 + k);
        s_w2[ci][dy][cp][dx] = pk(lo, hi);
    }
    cp_wait<0>();
    __syncthreads();

    #pragma unroll
    for (int ci = 0; ci < 3; ci++) {
        #pragma unroll
        for (int dy = 0; dy < 3; dy++) {
            const float* row = &s_in[ci][(ty+dy)*68 + tx*4];
            float4 q = *(const float4*)row;
            float v4 = row[4], v5 = row[5];
            u64 d0=pk(q.x,q.x), d1=pk(q.y,q.y), d2=pk(q.z,q.z), d3=pk(q.w,q.w), d4=pk(v4,v4), d5=pk(v5,v5);
            #pragma unroll
            for (int cp = 0; cp < 4; cp++) {
                const u64* wr = s_w2[ci][dy][cp];
                ulonglong2 w01 = *(const ulonglong2*)wr;
                u64 w2v = wr[2];
                acc[cp][0]=fma2(d0,w01.x,acc[cp][0]); acc[cp][1]=fma2(d1,w01.x,acc[cp][1]);
                acc[cp][2]=fma2(d2,w01.x,acc[cp][2]); acc[cp][3]=fma2(d3,w01.x,acc[cp][3]);
                acc[cp][0]=fma2(d1,w01.y,acc[cp][0]); acc[cp][1]=fma2(d2,w01.y,acc[cp][1]);
                acc[cp][2]=fma2(d3,w01.y,acc[cp][2]); acc[cp][3]=fma2(d4,w01.y,acc[cp][3]);
                acc[cp][0]=fma2(d2,w2v,acc[cp][0]);  acc[cp][1]=fma2(d3,w2v,acc[cp][1]);
                acc[cp][2]=fma2(d4,w2v,acc[cp][2]);  acc[cp][3]=fma2(d5,w2v,acc[cp][3]);
            }
        }
    }
    const int h = h0 + ty, w = w0 + tx*4;
    float bv[8];
    #pragma unroll
    for (int c = 0; c < 8; c++) bv[c] = bias[cog*8 + c];
    #pragma unroll
    for (int p = 0; p < 4; p++) {
        __align__(16) bf16 hi8[8];
        __align__(16) bf16 lo8[8];
        #pragma unroll
        for (int cp = 0; cp < 4; cp++) {
            float2 a = upk(acc[cp][p]);
            float v0 = fmaxf(a.x + bv[2*cp],   0.f);
            float v1 = fmaxf(a.y + bv[2*cp+1], 0.f);
            hi8[2*cp]   = __float2bfloat16(v0);
            lo8[2*cp]   = __float2bfloat16(v0 - __bfloat162float(hi8[2*cp]));
            hi8[2*cp+1] = __float2bfloat16(v1);
            lo8[2*cp+1] = __float2bfloat16(v1 - __bfloat162float(hi8[2*cp+1]));
        }
        size_t o = ((size_t)(n*S + h)*S + (w+p))*64 + cog*8;
        *(uint4*)(ohi + o) = *(uint4*)hi8;
        *(uint4*)(olo + o) = *(uint4*)lo8;
    }
}

// ---------------------------------------------------------------------------
// mma.sync implicit-GEMM conv with A-strip reuse across dx.
// Stage = (dy, chunk): load 130-pixel A strip (hi/lo) once + all 3 dx B tiles;
// compute 3 dx passes against the same strip via +dx row offset.
// Exact-fp32 activations x bf16 weights: D += Ahi*Bhi + Alo*Bhi.
// SMEM rows 144B stride (conflict-free ldmatrix). cp.async double buffer.
// ---------------------------------------------------------------------------
template<int NT>
__global__ __launch_bounds__(256, 1)
void conv_mma(const bf16* __restrict__ ihi, const bf16* __restrict__ ilo,
              const float* __restrict__ bias, bf16* __restrict__ ohi, bf16* __restrict__ olo,
              int CIN, int COUT, int S, int wbase)
{
    constexpr int WARPS_M = (NT == 128) ? 2 : 4;
    constexpr int MT = (NT == 128) ? 4 : 2;
    constexpr int MW = MT*16;
    constexpr uint32_t ASZ  = 132*144u;          // 130 rows used, padded
    constexpr uint32_t BSZ  = (uint32_t)NT*144u; // one dx B tile
    constexpr uint32_t BUFSZ = 2*ASZ + 3*BSZ;

    extern __shared__ __align__(16) char dsm[];
    const int tid = threadIdx.x;
    const int wid = tid >> 5, lane = tid & 31;
    const int wm = wid % WARPS_M, wn = wid / WARPS_M;
    const int ncog = COUT / NT;
    const int chunks = CIN >> 6;
    const int n = blockIdx.z / ncog, cog = blockIdx.z - n*ncog;
    const int w0 = blockIdx.x << 7;
    const int h = blockIdx.y;

    uint32_t sbase = ((uint32_t)__cvta_generic_to_shared(dsm) + 127u) & ~127u;
    const int NSt = 3*chunks;

    float acc[MT][4][4];
    #pragma unroll
    for (int mt = 0; mt < MT; mt++)
        #pragma unroll
        for (int nt = 0; nt < 4; nt++)
            { acc[mt][nt][0]=0.f; acc[mt][nt][1]=0.f; acc[mt][nt][2]=0.f; acc[mt][nt][3]=0.f; }

    const uint32_t rA = (uint32_t)(lane & 15)*144u + (uint32_t)(lane >> 4)*16u;
    const uint32_t rB = (uint32_t)((lane & 7) + ((lane >> 4) << 3))*144u
                      + (uint32_t)((lane >> 3) & 1)*16u;

    auto build = [&](int st, int fb) {
        uint32_t bo = sbase + (uint32_t)fb*BUFSZ;
        int dy = st / chunks, chunk = st - dy*chunks;
        int hh = h + dy - 1;
        bool hok = ((unsigned)hh < (unsigned)S);
        int hcl = hok ? hh : 0;
        // A strip: 130 rows (pixel w0-1+r), 8 x 16B segs, 2 terms
        for (int i = tid; i < 2080; i += 256) {
            int term = i / 1040, j = i - term*1040;
            int r = j >> 3, seg = j & 7;
            int wp = w0 + r - 1;
            bool ok = hok && ((unsigned)wp < (unsigned)S);
            int wcl = ok ? wp : 0;
            const bf16* src = term ? ilo : ihi;
            const void* g = src + ((size_t)(n*S + hcl)*S + wcl)*CIN + chunk*64 + seg*8;
            cp16(bo + (uint32_t)term*ASZ + (uint32_t)r*144u + (uint32_t)seg*16u, g, ok);
        }
        // B: all 3 dx tiles for this (dy, chunk)
        constexpr int bq = NT*8;
        for (int i = tid; i < 3*bq; i += 256) {
            int dx = i / bq, q = i - dx*bq;
            int shift = dy*3 + dx;
            size_t wblk = (size_t)wbase + (size_t)((shift*ncog + cog)*chunks + chunk)*((size_t)NT*64);
            cp16(bo + 2*ASZ + (uint32_t)dx*BSZ + (uint32_t)(q >> 3)*144u + (uint32_t)(q & 7)*16u,
                 g_wHi + wblk + (size_t)q*8, true);
        }
        cp_commit();
    };

    auto compute = [&](int fb) {
        uint32_t bo = sbase + (uint32_t)fb*BUFSZ;
        uint32_t Ah = bo, Al = bo + ASZ;
        #pragma unroll
        for (int dx = 0; dx < 3; dx++) {
            uint32_t Bb = bo + 2*ASZ + (uint32_t)dx*BSZ;
            uint32_t Ao = (uint32_t)dx*144u + rA;
            #pragma unroll
            for (int k16 = 0; k16 < 4; k16++) {
                uint32_t bf[2][4];
                #pragma unroll
                for (int p = 0; p < 2; p++)
                    ldsm4(bf[p], Bb + (uint32_t)(wn*32 + p*16)*144u + rB + (uint32_t)k16*32u);
                uint32_t af[MT][4];
                #pragma unroll
                for (int mt = 0; mt < MT; mt++)
                    ldsm4(af[mt], Ah + (uint32_t)(wm*MW + mt*16)*144u + Ao + (uint32_t)k16*32u);
                #pragma unroll
                for (int mt = 0; mt < MT; mt++)
                    #pragma unroll
                    for (int nt = 0; nt < 4; nt++)
                        mma16816(acc[mt][nt], af[mt], &bf[nt >> 1][(nt & 1)*2]);
                #pragma unroll
                for (int mt = 0; mt < MT; mt++)
                    ldsm4(af[mt], Al + (uint32_t)(wm*MW + mt*16)*144u + Ao + (uint32_t)k16*32u);
                #pragma unroll
                for (int mt = 0; mt < MT; mt++)
                    #pragma unroll
                    for (int nt = 0; nt < 4; nt++)
                        mma16816(acc[mt][nt], af[mt], &bf[nt >> 1][(nt & 1)*2]);
            }
        }
    };

    build(0, 0);
    for (int st = 0; st < NSt; st++) {
        int fb = st & 1;
        if (st + 1 < NSt) { build(st + 1, fb ^ 1); cp_wait<1>(); }
        else              { cp_wait<0>(); }
        __syncthreads();
        compute(fb);
        __syncthreads();
    }

    // Epilogue: bias + ReLU, NHWC hi/lo
    float b2[4][2];
    #pragma unroll
    for (int nt = 0; nt < 4; nt++) {
        int co = nt*8 + (lane & 3)*2;
        b2[nt][0] = bias[cog*NT + wn*32 + co];
        b2[nt][1] = bias[cog*NT + wn*32 + co + 1];
    }
    #pragma unroll
    for (int mt = 0; mt < MT; mt++) {
        int r0 = wm*MW + mt*16 + (lane >> 2);
        #pragma unroll
        for (int half = 0; half < 2; half++) {
            int px = w0 + r0 + half*8;
            size_t ob = ((size_t)(n*S + h)*S + px)*COUT + (size_t)(cog*NT + wn*32);
            #pragma unroll
            for (int nt = 0; nt < 4; nt++) {
                int co = nt*8 + (lane & 3)*2;
                float v0 = fmaxf(acc[mt][nt][half*2]   + b2[nt][0], 0.f);
                float v1 = fmaxf(acc[mt][nt][half*2+1] + b2[nt][1], 0.f);
                bf16 h0 = __float2bfloat16(v0);
                bf16 h1 = __float2bfloat16(v1);
                __nv_bfloat162 hp, lp;
                hp.x = h0; hp.y = h1;
                lp.x = __float2bfloat16(v0 - __bfloat162float(h0));
                lp.y = __float2bfloat16(v1 - __bfloat162float(h1));
                *(__nv_bfloat162*)(ohi + ob + co) = hp;
                *(__nv_bfloat162*)(olo + ob + co) = lp;
            }
        }
    }
}

// Pool: NHWC hi/lo -> NCHW fp32 + optional NHWC hi/lo
__global__ void pool_mma(const bf16* __restrict__ ihi, const bf16* __restrict__ ilo,
                         float* __restrict__ pout, bf16* __restrict__ ohi, bf16* __restrict__ olo,
                         int C, int S, int writeN)
{
    const int So = S >> 1;
    const size_t total = (size_t)6*So*So*C;
    const size_t stride = (size_t)gridDim.x*blockDim.x;
    for (size_t i = blockIdx.x*(size_t)blockDim.x + threadIdx.x; i < total; i += stride) {
        int c = (int)(i % C);
        size_t t = i / C;
        int xo = (int)(t % So); t /= So;
        int yo = (int)(t % So);
        int n = (int)(t / So);
        size_t b00 = ((size_t)(n*S + 2*yo)*S + 2*xo)*C + c;
        size_t b10 = b00 + (size_t)S*C;
        float v00 = __bfloat162float(ihi[b00])   + __bfloat162float(ilo[b00]);
        float v01 = __bfloat162float(ihi[b00+C]) + __bfloat162float(ilo[b00+C]);
        float v10 = __bfloat162float(ihi[b10])   + __bfloat162float(ilo[b10]);
        float v11 = __bfloat162float(ihi[b10+C]) + __bfloat162float(ilo[b10+C]);
        float m = fmaxf(fmaxf(v00, v01), fmaxf(v10, v11));
        pout[((size_t)(n*C + c)*So + yo)*So + xo] = m;
        if (writeN) {
            size_t o = ((size_t)(n*So + yo)*So + xo)*C + c;
            bf16 hh = __float2bfloat16(m);
            ohi[o] = hh;
            olo[o] = __float2bfloat16(m - __bfloat162float(hh));
        }
    }
}

__global__ void perc_kernel(const float* __restrict__ p, int C, int S) {
    const size_t per = (size_t)C*S*S;
    const size_t total = 2*per;
    const size_t stride = (size_t)gridDim.x * blockDim.x;
    double s = 0.0;
    for (size_t i = blockIdx.x*(size_t)blockDim.x + threadIdx.x; i < total; i += stride) {
        float po = p[i], pg = p[i + 2*per], pc = p[i + 4*per];
        s += (double)(fabsf(po-pg) + fabsf(pc-pg));
    }
    s = blockReduceSum(s);
    if (threadIdx.x == 0) atomicAdd(&g_acc[2], s);
}

__global__ __launch_bounds__(256, 2)
void style_kernel(const float* __restrict__ p, int C, int S, int va, double scale) {
    const int tid = threadIdx.x;
    const int tx = tid & 15, ty = tid >> 4;
    const int bc = blockIdx.z;
    const int b = bc / C, c = bc - b*C;
    const int wt = blockIdx.y * 64, vt = blockIdx.x * 64;
    const float* A = p + ((size_t)((va*2+b)*C + c)) * S * S;
    const float* G = p + ((size_t)((2   +b)*C + c)) * S * S;

    __shared__ __align__(16) float s_aw[32][64], s_av[32][64];
    __shared__ __align__(16) float s_gw[32][64], s_gv[32][64];

    u64 accA[4][2], accG[4][2];
    #pragma unroll
    for (int i = 0; i < 4; i++) { accA[i][0]=0; accA[i][1]=0; accG[i][0]=0; accG[i][1]=0; }

    for (int k0 = 0; k0 < S; k0 += 32) {
        __syncthreads();
        for (int i = tid; i < 32*64; i += 256) {
            int kk = i >> 6, col = i & 63;
            size_t row = (size_t)(k0+kk)*S;
            s_aw[kk][col] = A[row + wt + col];
            s_av[kk][col] = A[row + vt + col];
            s_gw[kk][col] = G[row + wt + col];
            s_gv[kk][col] = G[row + vt + col];
        }
        __syncthreads();
        #pragma unroll 4
        for (int kk = 0; kk < 32; kk++) {
            float4 aw4 = *(const float4*)&s_aw[kk][ty*4];
            float4 gw4 = *(const float4*)&s_gw[kk][ty*4];
            ulonglong2 av = *(const ulonglong2*)&s_av[kk][tx*4];
            ulonglong2 gv = *(const ulonglong2*)&s_gv[kk][tx*4];
            u64 aw[4] = {pk(aw4.x,aw4.x), pk(aw4.y,aw4.y), pk(aw4.z,aw4.z), pk(aw4.w,aw4.w)};
            u64 gw[4] = {pk(gw4.x,gw4.x), pk(gw4.y,gw4.y), pk(gw4.z,gw4.z), pk(gw4.w,gw4.w)};
            #pragma unroll
            for (int i = 0; i < 4; i++) {
                accA[i][0] = fma2(aw[i], av.x, accA[i][0]);
                accA[i][1] = fma2(aw[i], av.y, accA[i][1]);
                accG[i][0] = fma2(gw[i], gv.x, accG[i][0]);
                accG[i][1] = fma2(gw[i], gv.y, accG[i][1]);
            }
        }
    }
    double s = 0.0;
    #pragma unroll
    for (int i = 0; i < 4; i++) {
        #pragma unroll
        for (int j = 0; j < 2; j++) {
            float2 a = upk(accA[i][j]), g = upk(accG[i][j]);
            s += (double)fabsf(a.x - g.x) + (double)fabsf(a.y - g.y);
        }
    }
    s = blockReduceSum(s);
    if (threadIdx.x == 0) atomicAdd(&g_acc[3], scale * s);
}

__global__ void finish_kernel(float* __restrict__ out) {
    const double N    = 3.0*512.0*512.0*2.0;
    const double Nigt = 2.0*64.0*256.0*256.0;
    out[0] = (float)(2.0*g_acc[0]/N + g_acc[1]/N + g_acc[2]/Nigt + g_acc[3]);
}

extern "C" void kernel_launch(void* const* d_in, const int* in_sizes, int n_in,
                              void* d_out, int out_size) {
    const float* igt  = (const float*)d_in[0];
    const float* iout = (const float*)d_in[1];
    const float* mask = (const float*)d_in[2];
    const float* w[7]; const float* bs[7];
    for (int i = 0; i < 7; i++) { w[i] = (const float*)d_in[3+2*i]; bs[i] = (const float*)d_in[4+2*i]; }

    float *x0, *p1, *p2, *p3;
    bf16 *hA, *lA, *hB, *lB;
    cudaGetSymbolAddress((void**)&x0, g_x0);
    cudaGetSymbolAddress((void**)&p1, g_p1);
    cudaGetSymbolAddress((void**)&p2, g_p2);
    cudaGetSymbolAddress((void**)&p3, g_p3);
    cudaGetSymbolAddress((void**)&hA, g_hA);
    cudaGetSymbolAddress((void**)&lA, g_lA);
    cudaGetSymbolAddress((void**)&hB, g_hB);
    cudaGetSymbolAddress((void**)&lB, g_lB);

    const int SM64  = 2*(2*132*144 + 3*64*144)  + 128;   // 131456
    const int SM128 = 2*(2*132*144 + 3*128*144) + 128;   // 186752
    cudaFuncSetAttribute(conv_mma<64>,  cudaFuncAttributeMaxDynamicSharedMemorySize, SM64);
    cudaFuncSetAttribute(conv_mma<128>, cudaFuncAttributeMaxDynamicSharedMemorySize, SM128);

    zero_acc<<<1, 32>>>();
    prep_kernel<<<2048, 256>>>(igt, iout, mask);

    prep_w<<<128, 256>>>(w[1],  64,  64,  64, 0);
    prep_w<<<128, 256>>>(w[2],  64, 128, 128, 36864);
    prep_w<<<128, 256>>>(w[3], 128, 128, 128, 110592);
    prep_w<<<256, 256>>>(w[4], 128, 256, 128, 258048);
    prep_w<<<256, 256>>>(w[5], 256, 256, 128, 552960);
    prep_w<<<256, 256>>>(w[6], 256, 256, 128, 1142784);

    conv_l0<<<dim3(8,32,48), 256>>>(x0, w[0], bs[0], hA, lA, 512);

    conv_mma<64> <<<dim3(4,512,6),  256, SM64 >>>(hA, lA, bs[1], hB, lB,  64,  64, 512, 0);
    pool_mma<<<4096, 256>>>(hB, lB, p1, hA, lA, 64, 512, 1);
    conv_mma<128><<<dim3(2,256,6),  256, SM128>>>(hA, lA, bs[2], hB, lB,  64, 128, 256, 36864);
    conv_mma<128><<<dim3(2,256,6),  256, SM128>>>(hB, lB, bs[3], hA, lA, 128, 128, 256, 110592);
    pool_mma<<<2048, 256>>>(hA, lA, p2, hB, lB, 128, 256, 1);
    conv_mma<128><<<dim3(1,128,12), 256, SM128>>>(hB, lB, bs[4], hA, lA, 128, 256, 128, 258048);
    conv_mma<128><<<dim3(1,128,12), 256, SM128>>>(hA, lA, bs[5], hB, lB, 256, 256, 128, 552960);
    conv_mma<128><<<dim3(1,128,12), 256, SM128>>>(hB, lB, bs[6], hA, lA, 256, 256, 128, 1142784);
    pool_mma<<<1024, 256>>>(hA, lA, p3, hB, lB, 256, 128, 0);

    perc_kernel<<<2048, 256>>>(p1,  64, 256);
    perc_kernel<<<2048, 256>>>(p2, 128, 128);
    perc_kernel<<<1024, 256>>>(p3, 256,  64);

    const double s1 = 1.0/((double)64 *256*256)/( 64.0* 64.0);
    const double s2 = 1.0/((double)128*128*128)/(128.0*128.0);
    const double s3 = 1.0/((double)256* 64* 64)/(256.0*256.0);
    style_kernel<<<dim3(4,4,128), 256>>>(p1,  64, 256, 2, s1);
    style_kernel<<<dim3(4,4,128), 256>>>(p1,  64, 256, 0, s1);
    style_kernel<<<dim3(2,2,256), 256>>>(p2, 128, 128, 2, s2);
    style_kernel<<<dim3(2,2,256), 256>>>(p2, 128, 128, 0, s2);
    style_kernel<<<dim3(1,1,512), 256>>>(p3, 256,  64, 2, s3);
    style_kernel<<<dim3(1,1,512), 256>>>(p3, 256,  64, 0, s3);

    finish_kernel<<<1, 1>>>((float*)d_out);
}

// round 17
// speedup vs baseline: 7.5388x; 1.0573x over previous
#include <cuda_runtime.h>
#include <cuda_bf16.h>
#include <math.h>
#include <stdint.h>

#define HW0 (512*512)
typedef unsigned long long u64;
typedef __nv_bfloat16 bf16;

__device__ float g_x0  [6*3*HW0];
__device__ float g_p1  [6*64*256*256];
__device__ float g_p2  [6*128*128*128];
__device__ float g_p3  [6*256*64*64];
__device__ double g_acc[4];
__device__ bf16 g_hA[100663296];
__device__ bf16 g_lA[100663296];
__device__ bf16 g_hB[100663296];
__device__ bf16 g_lB[100663296];
__device__ bf16 g_wHi[1732608];

__device__ __forceinline__ u64 pk(float lo, float hi) {
    u64 r; asm("mov.b64 %0,{%1,%2};" : "=l"(r) : "f"(lo), "f"(hi)); return r;
}
__device__ __forceinline__ float2 upk(u64 v) {
    float2 r; asm("mov.b64 {%0,%1},%2;" : "=f"(r.x), "=f"(r.y) : "l"(v)); return r;
}
__device__ __forceinline__ u64 fma2(u64 a, u64 b, u64 c) {
    u64 d; asm("fma.rn.f32x2 %0,%1,%2,%3;" : "=l"(d) : "l"(a), "l"(b), "l"(c)); return d;
}
__device__ __forceinline__ void cp4(uint32_t s, const float* g, bool ok) {
    asm volatile("cp.async.ca.shared.global [%0],[%1],4,%2;" :: "r"(s), "l"(g), "r"(ok?4:0));
}
__device__ __forceinline__ void cp16(uint32_t s, const void* g, bool ok) {
    asm volatile("cp.async.cg.shared.global [%0],[%1],16,%2;" :: "r"(s), "l"(g), "r"(ok?16:0));
}
__device__ __forceinline__ void cp_commit() { asm volatile("cp.async.commit_group;"); }
template<int N> __device__ __forceinline__ void cp_wait() {
    asm volatile("cp.async.wait_group %0;" :: "n"(N));
}
__device__ __forceinline__ void ldsm4(uint32_t* r, uint32_t a) {
    asm volatile("ldmatrix.sync.aligned.m8n8.x4.shared.b16 {%0,%1,%2,%3},[%4];"
        : "=r"(r[0]), "=r"(r[1]), "=r"(r[2]), "=r"(r[3]) : "r"(a));
}
__device__ __forceinline__ void ldsm4t(uint32_t* r, uint32_t a) {
    asm volatile("ldmatrix.sync.aligned.m8n8.x4.trans.shared.b16 {%0,%1,%2,%3},[%4];"
        : "=r"(r[0]), "=r"(r[1]), "=r"(r[2]), "=r"(r[3]) : "r"(a));
}
__device__ __forceinline__ void mma16816(float* c, const uint32_t* a, const uint32_t* b) {
    asm volatile("mma.sync.aligned.m16n8k16.row.col.f32.bf16.bf16.f32 "
        "{%0,%1,%2,%3},{%4,%5,%6,%7},{%8,%9},{%0,%1,%2,%3};"
        : "+f"(c[0]), "+f"(c[1]), "+f"(c[2]), "+f"(c[3])
        : "r"(a[0]), "r"(a[1]), "r"(a[2]), "r"(a[3]), "r"(b[0]), "r"(b[1]));
}
__device__ __forceinline__ uint32_t pk2bf(bf16 a, bf16 b) {
    return (uint32_t)__bfloat16_as_ushort(a) | ((uint32_t)__bfloat16_as_ushort(b) << 16);
}

__device__ __forceinline__ double blockReduceSum(double v) {
    __shared__ double s[32];
    int lane = threadIdx.x & 31, wid = threadIdx.x >> 5;
    #pragma unroll
    for (int o = 16; o; o >>= 1) v += __shfl_down_sync(0xffffffffu, v, o);
    if (lane == 0) s[wid] = v;
    __syncthreads();
    int nw = blockDim.x >> 5;
    v = (threadIdx.x < nw) ? s[threadIdx.x] : 0.0;
    if (wid == 0) {
        #pragma unroll
        for (int o = 16; o; o >>= 1) v += __shfl_down_sync(0xffffffffu, v, o);
    }
    return v;
}

__global__ void zero_acc() { if (threadIdx.x < 4) g_acc[threadIdx.x] = 0.0; }

__global__ void prep_kernel(const float* __restrict__ igt, const float* __restrict__ iout,
                            const float* __restrict__ mask) {
    double hole = 0.0, valid = 0.0;
    const int total = 2*3*HW0;
    int stride = gridDim.x * blockDim.x;
    for (int i = blockIdx.x*blockDim.x + threadIdx.x; i < total; i += stride) {
        int hw = i % HW0, t = i / HW0, b = t / 3;
        float g = igt[i], o = iout[i];
        float mv = mask[b*HW0 + hw];
        float ad = fabsf(o - g);
        bool m = (mv != 0.0f);
        if (m) valid += (double)ad; else hole += (double)ad;
        g_x0[i] = o; g_x0[i + 6*HW0] = g; g_x0[i + 12*HW0] = m ? g : o;
    }
    hole = blockReduceSum(hole);
    __syncthreads();
    valid = blockReduceSum(valid);
    if (threadIdx.x == 0) { atomicAdd(&g_acc[0], hole); atomicAdd(&g_acc[1], valid); }
}

// Weight prepack: fp32 OIHW -> hi bf16 blocks [k9][cog][chunk]: N rows x 64 ci
__global__ void prep_w(const float* __restrict__ w, int CIN, int COUT, int N, int base) {
    int ncog = COUT / N, chunks = CIN >> 6;
    int total = 9*COUT*CIN;
    int stride = gridDim.x*blockDim.x;
    for (int i = blockIdx.x*blockDim.x + threadIdx.x; i < total; i += stride) {
        int inner = i % (N*64), blk = i / (N*64);
        int chunk = blk % chunks; int r1 = blk / chunks;
        int cog = r1 % ncog; int k9 = r1 / ncog;
        int row = inner >> 6, ci = inner & 63;
        int co = cog*N + row, c = chunk*64 + ci;
        int dy = k9/3, dx = k9 - dy*3;
        float v = w[((size_t)(co*CIN + c)*3 + dy)*3 + dx];
        g_wHi[(size_t)base + (size_t)blk*(N*64) + inner] = __float2bfloat16(v);
    }
}

// L0 direct FFMA2 conv (CIN=3), writes NHWC hi/lo bf16 directly
__global__ __launch_bounds__(256, 3)
void conv_l0(const float* __restrict__ in, const float* __restrict__ wgt,
             const float* __restrict__ bias, bf16* __restrict__ ohi,
             bf16* __restrict__ olo, int S)
{
    const int CIN = 3, COUT = 64;
    __shared__ __align__(16) float s_in[4][18*68];
    __shared__ __align__(16) u64 s_w2[4][3][4][4];
    const int tid = threadIdx.x;
    const int tx = tid & 15, ty = tid >> 4;
    const int n = blockIdx.z >> 3, cog = blockIdx.z & 7;
    const int w0 = blockIdx.x*64, h0 = blockIdx.y*16;
    const float* inb = in + (size_t)n*CIN*S*S;
    const float* wb = wgt + (size_t)(cog*8)*CIN*9;

    u64 acc[4][4];
    #pragma unroll
    for (int cp = 0; cp < 4; cp++) { acc[cp][0]=0; acc[cp][1]=0; acc[cp][2]=0; acc[cp][3]=0; }

    uint32_t sb = (uint32_t)__cvta_generic_to_shared(&s_in[0][0]);
    for (int i = tid; i < 3*1188; i += 256) {
        int ci = i/1188, rem = i - ci*1188;
        int r = rem/66, c = rem - r*66;
        int h = h0 + r - 1, w = w0 + c - 1;
        bool ok = ((unsigned)h < (unsigned)S) & ((unsigned)w < (unsigned)S);
        const float* g = ok ? inb + ((size_t)ci*S + h)*S + w : inb;
        cp4(sb + (uint32_t)((ci*18 + r)*68 + c)*4u, g, ok);
    }
    cp_commit();
    if (tid < 108) {
        int cp = tid/27, rem = tid - cp*27, ci = rem/9, k = rem - ci*9;
        int dy = k/3, dx = k - dy*3;
        float lo = __ldg(wb + (size_t)(2*cp)*27 + (size_t)ci*9 + k);
        float hi = __ldg(wb + (size_t)(2*cp+1)*27 + (size_t)ci*9 + k);
        s_w2[ci][dy][cp][dx] = pk(lo, hi);
    }
    cp_wait<0>();
    __syncthreads();

    #pragma unroll
    for (int ci = 0; ci < 3; ci++) {
        #pragma unroll
        for (int dy = 0; dy < 3; dy++) {
            const float* row = &s_in[ci][(ty+dy)*68 + tx*4];
            float4 q = *(const float4*)row;
            float v4 = row[4], v5 = row[5];
            u64 d0=pk(q.x,q.x), d1=pk(q.y,q.y), d2=pk(q.z,q.z), d3=pk(q.w,q.w), d4=pk(v4,v4), d5=pk(v5,v5);
            #pragma unroll
            for (int cp = 0; cp < 4; cp++) {
                const u64* wr = s_w2[ci][dy][cp];
                ulonglong2 w01 = *(const ulonglong2*)wr;
                u64 w2v = wr[2];
                acc[cp][0]=fma2(d0,w01.x,acc[cp][0]); acc[cp][1]=fma2(d1,w01.x,acc[cp][1]);
                acc[cp][2]=fma2(d2,w01.x,acc[cp][2]); acc[cp][3]=fma2(d3,w01.x,acc[cp][3]);
                acc[cp][0]=fma2(d1,w01.y,acc[cp][0]); acc[cp][1]=fma2(d2,w01.y,acc[cp][1]);
                acc[cp][2]=fma2(d3,w01.y,acc[cp][2]); acc[cp][3]=fma2(d4,w01.y,acc[cp][3]);
                acc[cp][0]=fma2(d2,w2v,acc[cp][0]);  acc[cp][1]=fma2(d3,w2v,acc[cp][1]);
                acc[cp][2]=fma2(d4,w2v,acc[cp][2]);  acc[cp][3]=fma2(d5,w2v,acc[cp][3]);
            }
        }
    }
    const int h = h0 + ty, w = w0 + tx*4;
    float bv[8];
    #pragma unroll
    for (int c = 0; c < 8; c++) bv[c] = bias[cog*8 + c];
    #pragma unroll
    for (int p = 0; p < 4; p++) {
        __align__(16) bf16 hi8[8];
        __align__(16) bf16 lo8[8];
        #pragma unroll
        for (int cp = 0; cp < 4; cp++) {
            float2 a = upk(acc[cp][p]);
            float v0 = fmaxf(a.x + bv[2*cp],   0.f);
            float v1 = fmaxf(a.y + bv[2*cp+1], 0.f);
            hi8[2*cp]   = __float2bfloat16(v0);
            lo8[2*cp]   = __float2bfloat16(v0 - __bfloat162float(hi8[2*cp]));
            hi8[2*cp+1] = __float2bfloat16(v1);
            lo8[2*cp+1] = __float2bfloat16(v1 - __bfloat162float(hi8[2*cp+1]));
        }
        size_t o = ((size_t)(n*S + h)*S + (w+p))*64 + cog*8;
        *(uint4*)(ohi + o) = *(uint4*)hi8;
        *(uint4*)(olo + o) = *(uint4*)lo8;
    }
}

// ---------------------------------------------------------------------------
// mma.sync implicit-GEMM conv with A-strip reuse across dx (R15 winner).
// ---------------------------------------------------------------------------
template<int NT>
__global__ __launch_bounds__(256, 1)
void conv_mma(const bf16* __restrict__ ihi, const bf16* __restrict__ ilo,
              const float* __restrict__ bias, bf16* __restrict__ ohi, bf16* __restrict__ olo,
              int CIN, int COUT, int S, int wbase)
{
    constexpr int WARPS_M = (NT == 128) ? 2 : 4;
    constexpr int MT = (NT == 128) ? 4 : 2;
    constexpr int MW = MT*16;
    constexpr uint32_t ASZ  = 132*144u;
    constexpr uint32_t BSZ  = (uint32_t)NT*144u;
    constexpr uint32_t BUFSZ = 2*ASZ + 3*BSZ;

    extern __shared__ __align__(16) char dsm[];
    const int tid = threadIdx.x;
    const int wid = tid >> 5, lane = tid & 31;
    const int wm = wid % WARPS_M, wn = wid / WARPS_M;
    const int ncog = COUT / NT;
    const int chunks = CIN >> 6;
    const int n = blockIdx.z / ncog, cog = blockIdx.z - n*ncog;
    const int w0 = blockIdx.x << 7;
    const int h = blockIdx.y;

    uint32_t sbase = ((uint32_t)__cvta_generic_to_shared(dsm) + 127u) & ~127u;
    const int NSt = 3*chunks;

    float acc[MT][4][4];
    #pragma unroll
    for (int mt = 0; mt < MT; mt++)
        #pragma unroll
        for (int nt = 0; nt < 4; nt++)
            { acc[mt][nt][0]=0.f; acc[mt][nt][1]=0.f; acc[mt][nt][2]=0.f; acc[mt][nt][3]=0.f; }

    const uint32_t rA = (uint32_t)(lane & 15)*144u + (uint32_t)(lane >> 4)*16u;
    const uint32_t rB = (uint32_t)((lane & 7) + ((lane >> 4) << 3))*144u
                      + (uint32_t)((lane >> 3) & 1)*16u;

    auto build = [&](int st, int fb) {
        uint32_t bo = sbase + (uint32_t)fb*BUFSZ;
        int dy = st / chunks, chunk = st - dy*chunks;
        int hh = h + dy - 1;
        bool hok = ((unsigned)hh < (unsigned)S);
        int hcl = hok ? hh : 0;
        for (int i = tid; i < 2080; i += 256) {
            int term = i / 1040, j = i - term*1040;
            int r = j >> 3, seg = j & 7;
            int wp = w0 + r - 1;
            bool ok = hok && ((unsigned)wp < (unsigned)S);
            int wcl = ok ? wp : 0;
            const bf16* src = term ? ilo : ihi;
            const void* g = src + ((size_t)(n*S + hcl)*S + wcl)*CIN + chunk*64 + seg*8;
            cp16(bo + (uint32_t)term*ASZ + (uint32_t)r*144u + (uint32_t)seg*16u, g, ok);
        }
        constexpr int bq = NT*8;
        for (int i = tid; i < 3*bq; i += 256) {
            int dx = i / bq, q = i - dx*bq;
            int shift = dy*3 + dx;
            size_t wblk = (size_t)wbase + (size_t)((shift*ncog + cog)*chunks + chunk)*((size_t)NT*64);
            cp16(bo + 2*ASZ + (uint32_t)dx*BSZ + (uint32_t)(q >> 3)*144u + (uint32_t)(q & 7)*16u,
                 g_wHi + wblk + (size_t)q*8, true);
        }
        cp_commit();
    };

    auto compute = [&](int fb) {
        uint32_t bo = sbase + (uint32_t)fb*BUFSZ;
        uint32_t Ah = bo, Al = bo + ASZ;
        #pragma unroll
        for (int dx = 0; dx < 3; dx++) {
            uint32_t Bb = bo + 2*ASZ + (uint32_t)dx*BSZ;
            uint32_t Ao = (uint32_t)dx*144u + rA;
            #pragma unroll
            for (int k16 = 0; k16 < 4; k16++) {
                uint32_t bf[2][4];
                #pragma unroll
                for (int p = 0; p < 2; p++)
                    ldsm4(bf[p], Bb + (uint32_t)(wn*32 + p*16)*144u + rB + (uint32_t)k16*32u);
                uint32_t af[MT][4];
                #pragma unroll
                for (int mt = 0; mt < MT; mt++)
                    ldsm4(af[mt], Ah + (uint32_t)(wm*MW + mt*16)*144u + Ao + (uint32_t)k16*32u);
                #pragma unroll
                for (int mt = 0; mt < MT; mt++)
                    #pragma unroll
                    for (int nt = 0; nt < 4; nt++)
                        mma16816(acc[mt][nt], af[mt], &bf[nt >> 1][(nt & 1)*2]);
                #pragma unroll
                for (int mt = 0; mt < MT; mt++)
                    ldsm4(af[mt], Al + (uint32_t)(wm*MW + mt*16)*144u + Ao + (uint32_t)k16*32u);
                #pragma unroll
                for (int mt = 0; mt < MT; mt++)
                    #pragma unroll
                    for (int nt = 0; nt < 4; nt++)
                        mma16816(acc[mt][nt], af[mt], &bf[nt >> 1][(nt & 1)*2]);
            }
        }
    };

    build(0, 0);
    for (int st = 0; st < NSt; st++) {
        int fb = st & 1;
        if (st + 1 < NSt) { build(st + 1, fb ^ 1); cp_wait<1>(); }
        else              { cp_wait<0>(); }
        __syncthreads();
        compute(fb);
        __syncthreads();
    }

    float b2[4][2];
    #pragma unroll
    for (int nt = 0; nt < 4; nt++) {
        int co = nt*8 + (lane & 3)*2;
        b2[nt][0] = bias[cog*NT + wn*32 + co];
        b2[nt][1] = bias[cog*NT + wn*32 + co + 1];
    }
    #pragma unroll
    for (int mt = 0; mt < MT; mt++) {
        int r0 = wm*MW + mt*16 + (lane >> 2);
        #pragma unroll
        for (int half = 0; half < 2; half++) {
            int px = w0 + r0 + half*8;
            size_t ob = ((size_t)(n*S + h)*S + px)*COUT + (size_t)(cog*NT + wn*32);
            #pragma unroll
            for (int nt = 0; nt < 4; nt++) {
                int co = nt*8 + (lane & 3)*2;
                float v0 = fmaxf(acc[mt][nt][half*2]   + b2[nt][0], 0.f);
                float v1 = fmaxf(acc[mt][nt][half*2+1] + b2[nt][1], 0.f);
                bf16 h0 = __float2bfloat16(v0);
                bf16 h1 = __float2bfloat16(v1);
                __nv_bfloat162 hp, lp;
                hp.x = h0; hp.y = h1;
                lp.x = __float2bfloat16(v0 - __bfloat162float(h0));
                lp.y = __float2bfloat16(v1 - __bfloat162float(h1));
                *(__nv_bfloat162*)(ohi + ob + co) = hp;
                *(__nv_bfloat162*)(olo + ob + co) = lp;
            }
        }
    }
}

// Pool: NHWC hi/lo -> NCHW fp32 + optional NHWC hi/lo
__global__ void pool_mma(const bf16* __restrict__ ihi, const bf16* __restrict__ ilo,
                         float* __restrict__ pout, bf16* __restrict__ ohi, bf16* __restrict__ olo,
                         int C, int S, int writeN)
{
    const int So = S >> 1;
    const size_t total = (size_t)6*So*So*C;
    const size_t stride = (size_t)gridDim.x*blockDim.x;
    for (size_t i = blockIdx.x*(size_t)blockDim.x + threadIdx.x; i < total; i += stride) {
        int c = (int)(i % C);
        size_t t = i / C;
        int xo = (int)(t % So); t /= So;
        int yo = (int)(t % So);
        int n = (int)(t / So);
        size_t b00 = ((size_t)(n*S + 2*yo)*S + 2*xo)*C + c;
        size_t b10 = b00 + (size_t)S*C;
        float v00 = __bfloat162float(ihi[b00])   + __bfloat162float(ilo[b00]);
        float v01 = __bfloat162float(ihi[b00+C]) + __bfloat162float(ilo[b00+C]);
        float v10 = __bfloat162float(ihi[b10])   + __bfloat162float(ilo[b10]);
        float v11 = __bfloat162float(ihi[b10+C]) + __bfloat162float(ilo[b10+C]);
        float m = fmaxf(fmaxf(v00, v01), fmaxf(v10, v11));
        pout[((size_t)(n*C + c)*So + yo)*So + xo] = m;
        if (writeN) {
            size_t o = ((size_t)(n*So + yo)*So + xo)*C + c;
            bf16 hh = __float2bfloat16(m);
            ohi[o] = hh;
            olo[o] = __float2bfloat16(m - __bfloat162float(hh));
        }
    }
}

__global__ void perc_kernel(const float* __restrict__ p, int C, int S) {
    const size_t per = (size_t)C*S*S;
    const size_t total = 2*per;
    const size_t stride = (size_t)gridDim.x * blockDim.x;
    double s = 0.0;
    for (size_t i = blockIdx.x*(size_t)blockDim.x + threadIdx.x; i < total; i += stride) {
        float po = p[i], pg = p[i + 2*per], pc = p[i + 4*per];
        s += (double)(fabsf(po-pg) + fabsf(pc-pg));
    }
    s = blockReduceSum(s);
    if (threadIdx.x == 0) atomicAdd(&g_acc[2], s);
}

// ---------------------------------------------------------------------------
// Style Gram-difference via mma.sync. Block = (bc, wtile, vtile): 64x64 tile
// of Gram(A) and Gram(G); K = S (h dim). Tiles stored natural [h][col] bf16
// hi/lo; fragments via ldmatrix.x4.trans. Since we only need sum|GA - GG|,
// the fragment->element mapping is irrelevant.
// Planes: 0=A-W.hi 1=A-W.lo 2=A-V.hi 3=A-V.lo 4=G-W.hi 5=G-W.lo 6=G-V.hi 7=G-V.lo
// ---------------------------------------------------------------------------
__global__ __launch_bounds__(256, 2)
void style_mma(const float* __restrict__ p, int C, int S, int va, double scale) {
    extern __shared__ __align__(16) char dsm[];
    const int tid = threadIdx.x;
    const int wid = tid >> 5, lane = tid & 31;
    const int wm = wid & 1, wn = wid >> 1;           // wm: 32-w half, wn: 16-v quarter
    const int bc = blockIdx.z;
    const int b = bc / C, c = bc - b*C;
    const int wt = blockIdx.y * 64, vt = blockIdx.x * 64;
    const float* A = p + ((size_t)((va*2+b)*C + c)) * S * S;
    const float* G = p + ((size_t)((2   +b)*C + c)) * S * S;

    uint32_t sb = (uint32_t)__cvta_generic_to_shared(dsm);

    float accA[2][2][4], accG[2][2][4];
    #pragma unroll
    for (int mt = 0; mt < 2; mt++)
        #pragma unroll
        for (int nt = 0; nt < 2; nt++)
            #pragma unroll
            for (int j = 0; j < 4; j++) { accA[mt][nt][j] = 0.f; accG[mt][nt][j] = 0.f; }

    const int rr = lane & 7, q = lane >> 3;
    // A-fragment (.trans) lane offset: rows h0 + (q>>1)*8 + rr, col + (q&1)*8
    const uint32_t oA = (uint32_t)((q >> 1)*8 + rr)*144u + (uint32_t)(q & 1)*16u;
    // B-fragment (.trans) lane offset: rows h0 + (q&1)*8 + rr, col + (q>>1)*8
    const uint32_t oB = (uint32_t)((q & 1)*8 + rr)*144u + (uint32_t)(q >> 1)*16u;

    for (int k0 = 0; k0 < S; k0 += 64) {
        // Fill: 4 (img,tile) pairs x 64 rows x 16 float4-cols
        for (int i = tid; i < 4096; i += 256) {
            int tile = i >> 10, rem = i & 1023, kk = rem >> 4, c4 = rem & 15;
            const float* src = (tile < 2) ? A : G;
            int tb = (tile & 1) ? vt : wt;
            float4 qv = *(const float4*)(src + (size_t)(k0 + kk)*S + tb + c4*4);
            bf16 h0 = __float2bfloat16(qv.x), h1 = __float2bfloat16(qv.y);
            bf16 h2 = __float2bfloat16(qv.z), h3 = __float2bfloat16(qv.w);
            bf16 l0 = __float2bfloat16(qv.x - __bfloat162float(h0));
            bf16 l1 = __float2bfloat16(qv.y - __bfloat162float(h1));
            bf16 l2 = __float2bfloat16(qv.z - __bfloat162float(h2));
            bf16 l3 = __float2bfloat16(qv.w - __bfloat162float(h3));
            uint32_t off = (uint32_t)kk*144u + (uint32_t)c4*8u;
            uint2* ph = (uint2*)(dsm + (tile*2    )*9216 + off);
            uint2* pl = (uint2*)(dsm + (tile*2 + 1)*9216 + off);
            *ph = make_uint2(pk2bf(h0, h1), pk2bf(h2, h3));
            *pl = make_uint2(pk2bf(l0, l1), pk2bf(l2, l3));
        }
        __syncthreads();

        #pragma unroll
        for (int k16 = 0; k16 < 4; k16++) {
            uint32_t hoff = (uint32_t)(k16*16)*144u;
            #pragma unroll
            for (int img = 0; img < 2; img++) {
                uint32_t pw = sb + (uint32_t)(img*4    )*9216 + hoff;  // W hi plane
                uint32_t pv = sb + (uint32_t)(img*4 + 2)*9216 + hoff;  // V hi plane
                uint32_t aw[2][2][4], bv[2][4];
                #pragma unroll
                for (int t = 0; t < 2; t++) {
                    #pragma unroll
                    for (int mt = 0; mt < 2; mt++)
                        ldsm4t(aw[t][mt], pw + (uint32_t)t*9216 + oA
                                         + (uint32_t)(wm*32 + mt*16)*2u);
                    ldsm4t(bv[t], pv + (uint32_t)t*9216 + oB + (uint32_t)(wn*16)*2u);
                }
                float (*acc)[2][4] = img ? accG : accA;
                #pragma unroll
                for (int mt = 0; mt < 2; mt++)
                    #pragma unroll
                    for (int nt = 0; nt < 2; nt++) {
                        mma16816(acc[mt][nt], aw[0][mt], &bv[0][nt*2]);  // hi*hi
                        mma16816(acc[mt][nt], aw[0][mt], &bv[1][nt*2]);  // hi*lo
                        mma16816(acc[mt][nt], aw[1][mt], &bv[0][nt*2]);  // lo*hi
                    }
            }
        }
        __syncthreads();
    }

    double s = 0.0;
    #pragma unroll
    for (int mt = 0; mt < 2; mt++)
        #pragma unroll
        for (int nt = 0; nt < 2; nt++)
            #pragma unroll
            for (int j = 0; j < 4; j++)
                s += (double)fabsf(accA[mt][nt][j] - accG[mt][nt][j]);
    s = blockReduceSum(s);
    if (threadIdx.x == 0) atomicAdd(&g_acc[3], scale * s);
}

__global__ void finish_kernel(float* __restrict__ out) {
    const double N    = 3.0*512.0*512.0*2.0;
    const double Nigt = 2.0*64.0*256.0*256.0;
    out[0] = (float)(2.0*g_acc[0]/N + g_acc[1]/N + g_acc[2]/Nigt + g_acc[3]);
}

extern "C" void kernel_launch(void* const* d_in, const int* in_sizes, int n_in,
                              void* d_out, int out_size) {
    const float* igt  = (const float*)d_in[0];
    const float* iout = (const float*)d_in[1];
    const float* mask = (const float*)d_in[2];
    const float* w[7]; const float* bs[7];
    for (int i = 0; i < 7; i++) { w[i] = (const float*)d_in[3+2*i]; bs[i] = (const float*)d_in[4+2*i]; }

    float *x0, *p1, *p2, *p3;
    bf16 *hA, *lA, *hB, *lB;
    cudaGetSymbolAddress((void**)&x0, g_x0);
    cudaGetSymbolAddress((void**)&p1, g_p1);
    cudaGetSymbolAddress((void**)&p2, g_p2);
    cudaGetSymbolAddress((void**)&p3, g_p3);
    cudaGetSymbolAddress((void**)&hA, g_hA);
    cudaGetSymbolAddress((void**)&lA, g_lA);
    cudaGetSymbolAddress((void**)&hB, g_hB);
    cudaGetSymbolAddress((void**)&lB, g_lB);

    const int SM64  = 2*(2*132*144 + 3*64*144)  + 128;   // 131456
    const int SM128 = 2*(2*132*144 + 3*128*144) + 128;   // 186752
    const int SMSTY = 8*9216;                            // 73728
    cudaFuncSetAttribute(conv_mma<64>,  cudaFuncAttributeMaxDynamicSharedMemorySize, SM64);
    cudaFuncSetAttribute(conv_mma<128>, cudaFuncAttributeMaxDynamicSharedMemorySize, SM128);
    cudaFuncSetAttribute(style_mma,     cudaFuncAttributeMaxDynamicSharedMemorySize, SMSTY);

    zero_acc<<<1, 32>>>();
    prep_kernel<<<2048, 256>>>(igt, iout, mask);

    prep_w<<<128, 256>>>(w[1],  64,  64,  64, 0);
    prep_w<<<128, 256>>>(w[2],  64, 128, 128, 36864);
    prep_w<<<128, 256>>>(w[3], 128, 128, 128, 110592);
    prep_w<<<256, 256>>>(w[4], 128, 256, 128, 258048);
    prep_w<<<256, 256>>>(w[5], 256, 256, 128, 552960);
    prep_w<<<256, 256>>>(w[6], 256, 256, 128, 1142784);

    conv_l0<<<dim3(8,32,48), 256>>>(x0, w[0], bs[0], hA, lA, 512);

    conv_mma<64> <<<dim3(4,512,6),  256, SM64 >>>(hA, lA, bs[1], hB, lB,  64,  64, 512, 0);
    pool_mma<<<4096, 256>>>(hB, lB, p1, hA, lA, 64, 512, 1);
    conv_mma<128><<<dim3(2,256,6),  256, SM128>>>(hA, lA, bs[2], hB, lB,  64, 128, 256, 36864);
    conv_mma<128><<<dim3(2,256,6),  256, SM128>>>(hB, lB, bs[3], hA, lA, 128, 128, 256, 110592);
    pool_mma<<<2048, 256>>>(hA, lA, p2, hB, lB, 128, 256, 1);
    conv_mma<128><<<dim3(1,128,12), 256, SM128>>>(hB, lB, bs[4], hA, lA, 128, 256, 128, 258048);
    conv_mma<128><<<dim3(1,128,12), 256, SM128>>>(hA, lA, bs[5], hB, lB, 256, 256, 128, 552960);
    conv_mma<128><<<dim3(1,128,12), 256, SM128>>>(hB, lB, bs[6], hA, lA, 256, 256, 128, 1142784);
    pool_mma<<<1024, 256>>>(hA, lA, p3, hB, lB, 256, 128, 0);

    perc_kernel<<<2048, 256>>>(p1,  64, 256);
    perc_kernel<<<2048, 256>>>(p2, 128, 128);
    perc_kernel<<<1024, 256>>>(p3, 256,  64);

    const double s1 = 1.0/((double)64 *256*256)/( 64.0* 64.0);
    const double s2 = 1.0/((double)128*128*128)/(128.0*128.0);
    const double s3 = 1.0/((double)256* 64* 64)/(256.0*256.0);
    style_mma<<<dim3(4,4,128), 256, SMSTY>>>(p1,  64, 256, 2, s1);
    style_mma<<<dim3(4,4,128), 256, SMSTY>>>(p1,  64, 256, 0, s1);
    style_mma<<<dim3(2,2,256), 256, SMSTY>>>(p2, 128, 128, 2, s2);
    style_mma<<<dim3(2,2,256), 256, SMSTY>>>(p2, 128, 128, 0, s2);
    style_mma<<<dim3(1,1,512), 256, SMSTY>>>(p3, 256,  64, 2, s3);
    style_mma<<<dim3(1,1,512), 256, SMSTY>>>(p3, 256,  64, 0, s3);

    finish_kernel<<<1, 1>>>((float*)d_out);
}